// round 1
// baseline (speedup 1.0000x reference)
#include <cuda_runtime.h>
#include <math.h>

// Problem constants
#define B_   2
#define S_   1024
#define D_   768
#define H_   12
#define DH_  64
#define DFF_ 3072
#define CH_  64
#define NC_  16
#define BS_  (B_*S_)                 // 2048
#define MREL (B_*NC_*CH_*CH_)        // 131072

// ---------------- scratch (device globals; no runtime allocation) ------------
__device__ float g_h  [BS_*D_];      // LN1 out, reused for LN2 out
__device__ float g_q  [BS_*D_];
__device__ float g_k  [BS_*D_];
__device__ float g_v  [BS_*D_];
__device__ float g_ctx[BS_*D_];
__device__ float g_x1 [BS_*D_];
__device__ float g_A  [BS_*D_];
__device__ float g_Bm [BS_*D_];
__device__ float g_x2 [BS_*D_];
__device__ float g_f  [BS_*DFF_];
__device__ float g_Hp [MREL*D_];     // 402 MB: relation-GEMM out; reused as attn scores

__device__ __forceinline__ float gelu_f(float x) {
    return 0.5f * x * (1.0f + erff(x * 0.70710678118654752f));
}

// ---------------- generic 128x128x8 SGEMM, C = A[MxK] @ W[KxN] (+epilogue) ---
template<bool BIAS, bool GELU_E, bool RES>
__launch_bounds__(256, 2)
__global__ void sgemm128(const float* __restrict__ A, const float* __restrict__ W,
                         const float* __restrict__ bias, const float* __restrict__ res,
                         float* __restrict__ C, int M, int N, int K) {
    __shared__ float As[8][128];
    __shared__ float Bs[8][128];
    const int t  = threadIdx.x;
    const int bm = blockIdx.y, bn = blockIdx.x;
    const int aRow = t >> 1, aK = (t & 1) * 4;
    const int bK   = t >> 5, bN = (t & 31) * 4;
    const int tx = t & 15, ty = t >> 4;
    const float* Aptr = A + (size_t)(bm * 128 + aRow) * K + aK;
    const float* Wptr = W + (size_t)bK * N + (size_t)bn * 128 + bN;
    float acc[8][8];
#pragma unroll
    for (int i = 0; i < 8; i++)
#pragma unroll
        for (int j = 0; j < 8; j++) acc[i][j] = 0.f;

    for (int k0 = 0; k0 < K; k0 += 8) {
        float4 av = *(const float4*)(Aptr + k0);
        float4 wv = *(const float4*)(Wptr + (size_t)k0 * N);
        As[aK+0][aRow] = av.x; As[aK+1][aRow] = av.y;
        As[aK+2][aRow] = av.z; As[aK+3][aRow] = av.w;
        *(float4*)&Bs[bK][bN] = wv;
        __syncthreads();
#pragma unroll
        for (int kk = 0; kk < 8; kk++) {
            float a[8], b[8];
            *(float4*)&a[0] = *(const float4*)&As[kk][ty*4];
            *(float4*)&a[4] = *(const float4*)&As[kk][64 + ty*4];
            *(float4*)&b[0] = *(const float4*)&Bs[kk][tx*4];
            *(float4*)&b[4] = *(const float4*)&Bs[kk][64 + tx*4];
#pragma unroll
            for (int i = 0; i < 8; i++)
#pragma unroll
                for (int j = 0; j < 8; j++) acc[i][j] += a[i] * b[j];
        }
        __syncthreads();
    }
#pragma unroll
    for (int i = 0; i < 8; i++) {
        int row = bm*128 + ((i < 4) ? (ty*4 + i) : (64 + ty*4 + i - 4));
#pragma unroll
        for (int j = 0; j < 8; j++) {
            int col = bn*128 + ((j < 4) ? (tx*4 + j) : (64 + tx*4 + j - 4));
            float v = acc[i][j];
            if (BIAS)   v += bias[col];
            if (GELU_E) v  = gelu_f(v);
            if (RES)    v += res[(size_t)row * N + col];
            C[(size_t)row * N + col] = v;
        }
    }
}

// ---------------- relation GEMM: rows are gelu(A_i + B_j), N=K=768 -----------
__launch_bounds__(256, 2)
__global__ void relgemm(const float* __restrict__ Ar, const float* __restrict__ Br,
                        const float* __restrict__ W, const float* __restrict__ bias,
                        float* __restrict__ C) {
    const int N = D_, K = D_;
    __shared__ float As[8][128];
    __shared__ float Bs[8][128];
    const int t  = threadIdx.x;
    const int bm = blockIdx.y, bn = blockIdx.x;
    const int aRow = t >> 1, aK = (t & 1) * 4;
    const int bK   = t >> 5, bN = (t & 31) * 4;
    const int tx = t & 15, ty = t >> 4;

    const int m    = bm * 128 + aRow;        // virtual row index
    const int cb   = (m >> 12) << 6;         // (b*16+c)*64 base row in [B*S]
    const int arow = cb + ((m >> 6) & 63);   // i
    const int brow = cb + (m & 63);          // j
    const float* Ap = Ar + (size_t)arow * K + aK;
    const float* Bp = Br + (size_t)brow * K + aK;
    const float* Wp = W  + (size_t)bK * N + (size_t)bn * 128 + bN;

    float acc[8][8];
#pragma unroll
    for (int i = 0; i < 8; i++)
#pragma unroll
        for (int j = 0; j < 8; j++) acc[i][j] = 0.f;

    for (int k0 = 0; k0 < K; k0 += 8) {
        float4 av = *(const float4*)(Ap + k0);
        float4 bv = *(const float4*)(Bp + k0);
        float4 wv = *(const float4*)(Wp + (size_t)k0 * N);
        As[aK+0][aRow] = gelu_f(av.x + bv.x);
        As[aK+1][aRow] = gelu_f(av.y + bv.y);
        As[aK+2][aRow] = gelu_f(av.z + bv.z);
        As[aK+3][aRow] = gelu_f(av.w + bv.w);
        *(float4*)&Bs[bK][bN] = wv;
        __syncthreads();
#pragma unroll
        for (int kk = 0; kk < 8; kk++) {
            float a[8], b[8];
            *(float4*)&a[0] = *(const float4*)&As[kk][ty*4];
            *(float4*)&a[4] = *(const float4*)&As[kk][64 + ty*4];
            *(float4*)&b[0] = *(const float4*)&Bs[kk][tx*4];
            *(float4*)&b[4] = *(const float4*)&Bs[kk][64 + tx*4];
#pragma unroll
            for (int i = 0; i < 8; i++)
#pragma unroll
                for (int j = 0; j < 8; j++) acc[i][j] += a[i] * b[j];
        }
        __syncthreads();
    }
#pragma unroll
    for (int i = 0; i < 8; i++) {
        int row = bm*128 + ((i < 4) ? (ty*4 + i) : (64 + ty*4 + i - 4));
#pragma unroll
        for (int j = 0; j < 8; j++) {
            int col = bn*128 + ((j < 4) ? (tx*4 + j) : (64 + tx*4 + j - 4));
            C[(size_t)row * N + col] = acc[i][j] + bias[col];
        }
    }
}

// ---------------- row LayerNorm (rows of width 768) --------------------------
__launch_bounds__(256)
__global__ void ln_kernel(const float* __restrict__ x, const float* __restrict__ g,
                          const float* __restrict__ b, float* __restrict__ out) {
    const int r = blockIdx.x, t = threadIdx.x;
    __shared__ float rs[8], rq[8], stat[2];
    const float* row = x + (size_t)r * D_;
    float v0 = row[t], v1 = row[t + 256], v2 = row[t + 512];
    float s = v0 + v1 + v2;
    float q = v0*v0 + v1*v1 + v2*v2;
#pragma unroll
    for (int o = 16; o > 0; o >>= 1) {
        s += __shfl_xor_sync(0xffffffffu, s, o);
        q += __shfl_xor_sync(0xffffffffu, q, o);
    }
    if ((t & 31) == 0) { rs[t >> 5] = s; rq[t >> 5] = q; }
    __syncthreads();
    if (t == 0) {
        float S = 0.f, Q = 0.f;
        for (int w = 0; w < 8; w++) { S += rs[w]; Q += rq[w]; }
        float mean = S * (1.f/768.f);
        float var  = Q * (1.f/768.f) - mean*mean;
        stat[0] = mean; stat[1] = rsqrtf(var + 1e-5f);
    }
    __syncthreads();
    float mean = stat[0], rstd = stat[1];
    float* o = out + (size_t)r * D_;
    o[t]       = (v0 - mean) * rstd * g[t]       + b[t];
    o[t + 256] = (v1 - mean) * rstd * g[t + 256] + b[t + 256];
    o[t + 512] = (v2 - mean) * rstd * g[t + 512] + b[t + 512];
}

// ---------------- attention: S = Q Kᵀ / 8 ------------------------------------
__launch_bounds__(256)
__global__ void qk_kernel(const float* __restrict__ q, const float* __restrict__ k,
                          float* __restrict__ sc) {
    const int bh = blockIdx.z;                  // b*12 + h
    const int qt = blockIdx.y, kt = blockIdx.x;
    const int t = threadIdx.x, tx = t & 15, ty = t >> 4;
    const float* qb = q + (size_t)(bh / H_) * S_ * D_ + (bh % H_) * DH_;
    const float* kb = k + (size_t)(bh / H_) * S_ * D_ + (bh % H_) * DH_;
    float* sb = sc + (size_t)bh * S_ * S_;
    __shared__ float Qs[64][65];
    __shared__ float Ks[64][65];
#pragma unroll
    for (int l = 0; l < 4; l++) {
        int idx = t + l * 256;
        int r = idx >> 4, d4 = (idx & 15) * 4;
        float4 a = *(const float4*)(qb + (size_t)(qt*64 + r) * D_ + d4);
        float4 c = *(const float4*)(kb + (size_t)(kt*64 + r) * D_ + d4);
        Qs[d4+0][r] = a.x; Qs[d4+1][r] = a.y; Qs[d4+2][r] = a.z; Qs[d4+3][r] = a.w;
        Ks[d4+0][r] = c.x; Ks[d4+1][r] = c.y; Ks[d4+2][r] = c.z; Ks[d4+3][r] = c.w;
    }
    __syncthreads();
    float acc[4][4] = {};
#pragma unroll 8
    for (int d = 0; d < 64; d++) {
        float a[4], b[4];
#pragma unroll
        for (int i = 0; i < 4; i++) { a[i] = Qs[d][ty*4+i]; b[i] = Ks[d][tx*4+i]; }
#pragma unroll
        for (int i = 0; i < 4; i++)
#pragma unroll
            for (int j = 0; j < 4; j++) acc[i][j] += a[i] * b[j];
    }
#pragma unroll
    for (int i = 0; i < 4; i++) {
        float4 o = make_float4(acc[i][0]*0.125f, acc[i][1]*0.125f,
                               acc[i][2]*0.125f, acc[i][3]*0.125f);
        *(float4*)(sb + (size_t)(qt*64 + ty*4 + i) * S_ + kt*64 + tx*4) = o;
    }
}

// ---------------- softmax over rows of 1024 (in place) -----------------------
__launch_bounds__(256)
__global__ void softmax_k(float* __restrict__ sc) {
    const int r = blockIdx.x, t = threadIdx.x;
    float* row = sc + (size_t)r * 1024;
    __shared__ float red[8], stat[1];
    float v0 = row[t], v1 = row[t+256], v2 = row[t+512], v3 = row[t+768];
    float m = fmaxf(fmaxf(v0, v1), fmaxf(v2, v3));
#pragma unroll
    for (int o = 16; o > 0; o >>= 1) m = fmaxf(m, __shfl_xor_sync(0xffffffffu, m, o));
    if ((t & 31) == 0) red[t >> 5] = m;
    __syncthreads();
    if (t == 0) {
        float M = red[0];
        for (int w = 1; w < 8; w++) M = fmaxf(M, red[w]);
        stat[0] = M;
    }
    __syncthreads();
    float M = stat[0];
    v0 = expf(v0 - M); v1 = expf(v1 - M); v2 = expf(v2 - M); v3 = expf(v3 - M);
    float s = v0 + v1 + v2 + v3;
#pragma unroll
    for (int o = 16; o > 0; o >>= 1) s += __shfl_xor_sync(0xffffffffu, s, o);
    __syncthreads();
    if ((t & 31) == 0) red[t >> 5] = s;
    __syncthreads();
    if (t == 0) {
        float S = 0.f;
        for (int w = 0; w < 8; w++) S += red[w];
        stat[0] = 1.f / S;
    }
    __syncthreads();
    float inv = stat[0];
    row[t] = v0*inv; row[t+256] = v1*inv; row[t+512] = v2*inv; row[t+768] = v3*inv;
}

// ---------------- ctx = attn @ V ---------------------------------------------
__launch_bounds__(256)
__global__ void av_kernel(const float* __restrict__ sc, const float* __restrict__ v,
                          float* __restrict__ ctx) {
    const int bh = blockIdx.y, qt = blockIdx.x;
    const int t = threadIdx.x, tx = t & 15, ty = t >> 4;
    const float* sb = sc + (size_t)bh * S_ * S_ + (size_t)qt * 64 * S_;
    const float* vb = v + (size_t)(bh / H_) * S_ * D_ + (bh % H_) * DH_;
    float* cb = ctx + (size_t)(bh / H_) * S_ * D_ + (bh % H_) * DH_;
    __shared__ float Ps[64][65];
    __shared__ float Vs[64][64];
    float acc[4][4] = {};
    for (int kt = 0; kt < 16; kt++) {
#pragma unroll
        for (int l = 0; l < 4; l++) {
            int idx = t + l * 256;
            int r = idx >> 4, c4 = (idx & 15) * 4;
            float4 p = *(const float4*)(sb + (size_t)r * S_ + kt*64 + c4);
            Ps[c4+0][r] = p.x; Ps[c4+1][r] = p.y; Ps[c4+2][r] = p.z; Ps[c4+3][r] = p.w;
            float4 w = *(const float4*)(vb + (size_t)(kt*64 + r) * D_ + c4);
            *(float4*)&Vs[r][c4] = w;
        }
        __syncthreads();
#pragma unroll 8
        for (int kk = 0; kk < 64; kk++) {
            float a[4], b[4];
#pragma unroll
            for (int i = 0; i < 4; i++) { a[i] = Ps[kk][ty*4+i]; b[i] = Vs[kk][tx*4+i]; }
#pragma unroll
            for (int i = 0; i < 4; i++)
#pragma unroll
                for (int j = 0; j < 4; j++) acc[i][j] += a[i] * b[j];
        }
        __syncthreads();
    }
#pragma unroll
    for (int i = 0; i < 4; i++) {
        float4 o = make_float4(acc[i][0], acc[i][1], acc[i][2], acc[i][3]);
        *(float4*)(cb + (size_t)(qt*64 + ty*4 + i) * D_ + tx*4) = o;
    }
}

// ---------------- per-(b,c,i): LN each j-row of Hp, mean over j, residual ----
__launch_bounds__(256)
__global__ void relreduce(const float* __restrict__ Hp, const float* __restrict__ g,
                          const float* __restrict__ bln, const float* __restrict__ x1,
                          float* __restrict__ x2) {
    const int bci = blockIdx.x;        // 0..2047 -> row of [B*S]
    const int t = threadIdx.x;
    __shared__ float rs[8], rq[8], stat[2];
    float a0 = 0.f, a1 = 0.f, a2 = 0.f;
    const float* base = Hp + (size_t)bci * 64 * D_;
    for (int j = 0; j < 64; j++) {
        const float* row = base + (size_t)j * D_;
        float v0 = row[t], v1 = row[t + 256], v2 = row[t + 512];
        float s = v0 + v1 + v2;
        float q = v0*v0 + v1*v1 + v2*v2;
#pragma unroll
        for (int o = 16; o > 0; o >>= 1) {
            s += __shfl_xor_sync(0xffffffffu, s, o);
            q += __shfl_xor_sync(0xffffffffu, q, o);
        }
        if ((t & 31) == 0) { rs[t >> 5] = s; rq[t >> 5] = q; }
        __syncthreads();
        if (t == 0) {
            float S = 0.f, Q = 0.f;
            for (int w = 0; w < 8; w++) { S += rs[w]; Q += rq[w]; }
            float mean = S * (1.f/768.f);
            float var  = Q * (1.f/768.f) - mean*mean;
            stat[0] = mean; stat[1] = rsqrtf(var + 1e-5f);
        }
        __syncthreads();
        float mean = stat[0], rstd = stat[1];
        a0 += (v0 - mean) * rstd;
        a1 += (v1 - mean) * rstd;
        a2 += (v2 - mean) * rstd;
        __syncthreads();
    }
    size_t o = (size_t)bci * D_;
    x2[o + t]       = x1[o + t]       + a0 * (1.f/64.f) * g[t]       + bln[t];
    x2[o + t + 256] = x1[o + t + 256] + a1 * (1.f/64.f) * g[t + 256] + bln[t + 256];
    x2[o + t + 512] = x1[o + t + 512] + a2 * (1.f/64.f) * g[t + 512] + bln[t + 512];
}

// ---------------- host orchestration -----------------------------------------
static float *P_h, *P_q, *P_k, *P_v, *P_ctx, *P_x1, *P_A, *P_Bm, *P_x2, *P_f, *P_Hp;
static bool g_init = false;

extern "C" void kernel_launch(void* const* d_in, const int* in_sizes, int n_in,
                              void* d_out, int out_size) {
    if (!g_init) {
        cudaGetSymbolAddress((void**)&P_h,   g_h);
        cudaGetSymbolAddress((void**)&P_q,   g_q);
        cudaGetSymbolAddress((void**)&P_k,   g_k);
        cudaGetSymbolAddress((void**)&P_v,   g_v);
        cudaGetSymbolAddress((void**)&P_ctx, g_ctx);
        cudaGetSymbolAddress((void**)&P_x1,  g_x1);
        cudaGetSymbolAddress((void**)&P_A,   g_A);
        cudaGetSymbolAddress((void**)&P_Bm,  g_Bm);
        cudaGetSymbolAddress((void**)&P_x2,  g_x2);
        cudaGetSymbolAddress((void**)&P_f,   g_f);
        cudaGetSymbolAddress((void**)&P_Hp,  g_Hp);
        g_init = true;
    }
    const float* x      = (const float*)d_in[0];
    const float* Wq     = (const float*)d_in[1];
    const float* bq     = (const float*)d_in[2];
    const float* Wk     = (const float*)d_in[3];
    const float* bk     = (const float*)d_in[4];
    const float* Wv     = (const float*)d_in[5];
    const float* bv     = (const float*)d_in[6];
    const float* Wo     = (const float*)d_in[7];
    const float* bo     = (const float*)d_in[8];
    const float* ln1_g  = (const float*)d_in[9];
    const float* ln1_b  = (const float*)d_in[10];
    const float* rel_W1 = (const float*)d_in[11];
    const float* rel_b1 = (const float*)d_in[12];
    const float* rel_W2 = (const float*)d_in[13];
    const float* rel_b2 = (const float*)d_in[14];
    const float* rel_ln_g = (const float*)d_in[15];
    const float* rel_ln_b = (const float*)d_in[16];
    const float* ln2_g  = (const float*)d_in[17];
    const float* ln2_b  = (const float*)d_in[18];
    const float* enc_W1 = (const float*)d_in[19];
    const float* enc_b1 = (const float*)d_in[20];
    const float* enc_W2 = (const float*)d_in[21];
    const float* enc_b2 = (const float*)d_in[22];
    float* out = (float*)d_out;

    // 1) h = LN1(x)
    ln_kernel<<<BS_, 256>>>(x, ln1_g, ln1_b, P_h);
    // 2) q,k,v projections
    dim3 g768(D_/128, BS_/128);
    sgemm128<true,false,false><<<g768, 256>>>(P_h, Wq, bq, nullptr, P_q, BS_, D_, D_);
    sgemm128<true,false,false><<<g768, 256>>>(P_h, Wk, bk, nullptr, P_k, BS_, D_, D_);
    sgemm128<true,false,false><<<g768, 256>>>(P_h, Wv, bv, nullptr, P_v, BS_, D_, D_);
    // 3) attention (scores staged in g_Hp)
    qk_kernel<<<dim3(16, 16, B_*H_), 256>>>(P_q, P_k, P_Hp);
    softmax_k<<<B_*H_*S_, 256>>>(P_Hp);
    av_kernel<<<dim3(16, B_*H_), 256>>>(P_Hp, P_v, P_ctx);
    // 4) x1 = x + ctx@Wo + bo
    sgemm128<true,false,true><<<g768, 256>>>(P_ctx, Wo, bo, x, P_x1, BS_, D_, D_);
    // 5) A = x1@W1a + b1 ;  Bm = x1@W1b
    sgemm128<true,false,false><<<g768, 256>>>(P_x1, rel_W1, rel_b1, nullptr, P_A, BS_, D_, D_);
    sgemm128<false,false,false><<<g768, 256>>>(P_x1, rel_W1 + D_*D_, nullptr, nullptr, P_Bm, BS_, D_, D_);
    // 6) relation pairwise GEMM + LN/mean reduction
    relgemm<<<dim3(D_/128, MREL/128), 256>>>(P_A, P_Bm, rel_W2, rel_b2, P_Hp);
    relreduce<<<BS_, 256>>>(P_Hp, rel_ln_g, rel_ln_b, P_x1, P_x2);
    // 7) FFN
    ln_kernel<<<BS_, 256>>>(P_x2, ln2_g, ln2_b, P_h);
    sgemm128<true,true,false><<<dim3(DFF_/128, BS_/128), 256>>>(P_h, enc_W1, enc_b1, nullptr, P_f, BS_, DFF_, D_);
    sgemm128<true,false,true><<<g768, 256>>>(P_f, enc_W2, enc_b2, P_x2, out, BS_, D_, DFF_);
}

// round 2
// speedup vs baseline: 2.0748x; 2.0748x over previous
#include <cuda_runtime.h>
#include <math.h>
#include <stdint.h>

#define B_   2
#define S_   1024
#define D_   768
#define H_   12
#define DFF_ 3072
#define BS_  2048
#define MREL 131072

// ---------------- scratch ----------------
__device__ float g_h  [BS_*D_];
__device__ float g_q  [BS_*D_];
__device__ float g_k  [BS_*D_];
__device__ float g_v  [BS_*D_];
__device__ float g_ctx[BS_*D_];
__device__ float g_x1 [BS_*D_];
__device__ float g_A  [BS_*D_];
__device__ float g_Bm [BS_*D_];
__device__ float g_x2 [BS_*D_];
__device__ float g_f  [BS_*DFF_];
__device__ float g_Hp [(size_t)MREL*D_];   // relation out; reused for attn scores

__device__ __forceinline__ float gelu_f(float x) {
    return 0.5f * x * (1.0f + erff(x * 0.70710678118654752f));
}
__device__ __forceinline__ float to_tf32(float x) {
    uint32_t u; asm("cvt.rna.tf32.f32 %0, %1;" : "=r"(u) : "f"(x));
    return __uint_as_float(u);
}
__device__ __forceinline__ void mma8(float* c, const uint32_t* a, const uint32_t* b) {
    asm volatile(
        "mma.sync.aligned.m16n8k8.row.col.f32.tf32.tf32.f32 "
        "{%0,%1,%2,%3},{%4,%5,%6,%7},{%8,%9},{%0,%1,%2,%3};\n"
        : "+f"(c[0]), "+f"(c[1]), "+f"(c[2]), "+f"(c[3])
        : "r"(a[0]), "r"(a[1]), "r"(a[2]), "r"(a[3]), "r"(b[0]), "r"(b[1]));
}

// EPI: 0=none 1=bias 2=bias+gelu 3=bias+res 4=*0.125
template<int EPI>
__device__ __forceinline__ void epi2(float* C, int ldc, const float* bias,
                                     const float* res, int row, int col,
                                     float v0, float v1) {
    if (EPI == 1 || EPI == 2 || EPI == 3) { v0 += bias[col]; v1 += bias[col+1]; }
    if (EPI == 2) { v0 = gelu_f(v0); v1 = gelu_f(v1); }
    if (EPI == 3) { size_t o = (size_t)row*ldc + col; v0 += res[o]; v1 += res[o+1]; }
    if (EPI == 4) { v0 *= 0.125f; v1 *= 0.125f; }
    *(float2*)(C + (size_t)row*ldc + col) = make_float2(v0, v1);
}

// ============= generic tf32 tensor-core GEMM: C = A[MxK] @ B[KxN] ============
// BTRANS: B stored [N][K] (row-major over N) instead of [K][N].
// Batched over blockIdx.z with (z/H, z%H) strides.
template<int EPI, bool BTRANS>
__global__ void __launch_bounds__(256)
gemm_tc(const float* __restrict__ A, const float* __restrict__ Bm_,
        const float* __restrict__ bias, const float* __restrict__ res,
        float* __restrict__ C, int M, int N, int K,
        int lda, int ldb, int ldc,
        long long aSB, long long aSH, long long bSB, long long bSH,
        long long cSB, long long cSH) {
    __shared__ float As[2][16][132];
    __shared__ float Bs[2][16][132];
    const int t = threadIdx.x, bm = blockIdx.y, bn = blockIdx.x, z = blockIdx.z;
    A   += (z / H_) * aSB + (z % H_) * aSH;
    Bm_ += (z / H_) * bSB + (z % H_) * bSH;
    C   += (z / H_) * cSB + (z % H_) * cSH;
    if (EPI == 3) res += (z / H_) * cSB + (z % H_) * cSH;
    const int lane = t & 31, wid = t >> 5;
    const int warpM = wid & 1, warpN = wid >> 1;
    const int g = lane >> 2, tg = lane & 3;
    const int aRow = t >> 2, aK4 = (t & 3) * 4;
    const float* Ap = A + (size_t)(bm * 128) * lda;

    float4 ra[2], rb[2];
    float acc[4][4][4];
#pragma unroll
    for (int i = 0; i < 4; i++)
#pragma unroll
        for (int j = 0; j < 4; j++)
#pragma unroll
            for (int c = 0; c < 4; c++) acc[i][j][c] = 0.f;

    auto gload = [&](int k0) {
#pragma unroll
        for (int p = 0; p < 2; p++)
            ra[p] = *(const float4*)(Ap + (size_t)(aRow + p*64) * lda + k0 + aK4);
        if (!BTRANS) {
#pragma unroll
            for (int p = 0; p < 2; p++) {
                int kr = (t >> 5) + p*8, n4 = (t & 31) * 4, col = bn*128 + n4;
                rb[p] = (col < N) ? *(const float4*)(Bm_ + (size_t)(k0 + kr) * ldb + col)
                                  : make_float4(0.f, 0.f, 0.f, 0.f);
            }
        } else {
#pragma unroll
            for (int p = 0; p < 2; p++) {
                int nr = (t >> 2) + p*64, k4 = (t & 3) * 4, col = bn*128 + nr;
                rb[p] = (col < N) ? *(const float4*)(Bm_ + (size_t)col * ldb + k0 + k4)
                                  : make_float4(0.f, 0.f, 0.f, 0.f);
            }
        }
    };
    auto sstore = [&](int buf) {
#pragma unroll
        for (int p = 0; p < 2; p++) {
            int r = aRow + p*64;
            As[buf][aK4+0][r] = to_tf32(ra[p].x);
            As[buf][aK4+1][r] = to_tf32(ra[p].y);
            As[buf][aK4+2][r] = to_tf32(ra[p].z);
            As[buf][aK4+3][r] = to_tf32(ra[p].w);
        }
        if (!BTRANS) {
#pragma unroll
            for (int p = 0; p < 2; p++) {
                int kr = (t >> 5) + p*8, n4 = (t & 31) * 4;
                Bs[buf][kr][n4+0] = to_tf32(rb[p].x);
                Bs[buf][kr][n4+1] = to_tf32(rb[p].y);
                Bs[buf][kr][n4+2] = to_tf32(rb[p].z);
                Bs[buf][kr][n4+3] = to_tf32(rb[p].w);
            }
        } else {
#pragma unroll
            for (int p = 0; p < 2; p++) {
                int nr = (t >> 2) + p*64, k4 = (t & 3) * 4;
                Bs[buf][k4+0][nr] = to_tf32(rb[p].x);
                Bs[buf][k4+1][nr] = to_tf32(rb[p].y);
                Bs[buf][k4+2][nr] = to_tf32(rb[p].z);
                Bs[buf][k4+3][nr] = to_tf32(rb[p].w);
            }
        }
    };
    auto compute = [&](int buf) {
#pragma unroll
        for (int kk = 0; kk < 16; kk += 8) {
            uint32_t af[4][4], bf[4][2];
#pragma unroll
            for (int mt = 0; mt < 4; mt++) {
                int m = warpM*64 + mt*16 + g;
                af[mt][0] = __float_as_uint(As[buf][kk+tg  ][m]);
                af[mt][1] = __float_as_uint(As[buf][kk+tg  ][m+8]);
                af[mt][2] = __float_as_uint(As[buf][kk+tg+4][m]);
                af[mt][3] = __float_as_uint(As[buf][kk+tg+4][m+8]);
            }
#pragma unroll
            for (int nt = 0; nt < 4; nt++) {
                int n = warpN*32 + nt*8 + g;
                bf[nt][0] = __float_as_uint(Bs[buf][kk+tg  ][n]);
                bf[nt][1] = __float_as_uint(Bs[buf][kk+tg+4][n]);
            }
#pragma unroll
            for (int mt = 0; mt < 4; mt++)
#pragma unroll
                for (int nt = 0; nt < 4; nt++) mma8(acc[mt][nt], af[mt], bf[nt]);
        }
    };

    const int nT = K >> 4;
    gload(0); sstore(0); __syncthreads();
    int buf = 0;
    for (int ti = 0; ti < nT; ++ti) {
        if (ti + 1 < nT) gload((ti + 1) << 4);
        compute(buf);
        if (ti + 1 < nT) sstore(buf ^ 1);
        __syncthreads();
        buf ^= 1;
    }
#pragma unroll
    for (int mt = 0; mt < 4; mt++)
#pragma unroll
        for (int nt = 0; nt < 4; nt++) {
            int row = bm*128 + warpM*64 + mt*16 + g;
            int col = bn*128 + warpN*32 + nt*8 + 2*tg;
            if (col < N) {
                epi2<EPI>(C, ldc, bias, res, row,     col, acc[mt][nt][0], acc[mt][nt][1]);
                epi2<EPI>(C, ldc, bias, res, row + 8, col, acc[mt][nt][2], acc[mt][nt][3]);
            }
        }
}

// ====== relation GEMM: virtual A rows gelu(Ar[i]+Br[j]) @ W2[768x768]+b ======
__global__ void __launch_bounds__(256)
relgemm_tc(const float* __restrict__ Ar, const float* __restrict__ Br,
           const float* __restrict__ W, const float* __restrict__ bias,
           float* __restrict__ C) {
    const int N = D_;
    __shared__ float As[2][16][132];
    __shared__ float Bs[2][16][132];
    const int t = threadIdx.x, bm = blockIdx.y, bn = blockIdx.x;
    const int lane = t & 31, wid = t >> 5;
    const int warpM = wid & 1, warpN = wid >> 1;
    const int g = lane >> 2, tg = lane & 3;
    const int aRow = t >> 2, aK4 = (t & 3) * 4;

    const float* pa[2]; const float* pb[2];
#pragma unroll
    for (int p = 0; p < 2; p++) {
        int m = bm*128 + aRow + p*64;
        int cb = (m >> 12) << 6;
        pa[p] = Ar + (size_t)(cb + ((m >> 6) & 63)) * D_ + aK4;
        pb[p] = Br + (size_t)(cb + (m & 63)) * D_ + aK4;
    }

    float4 ra[2], rb[2];
    float acc[4][4][4];
#pragma unroll
    for (int i = 0; i < 4; i++)
#pragma unroll
        for (int j = 0; j < 4; j++)
#pragma unroll
            for (int c = 0; c < 4; c++) acc[i][j][c] = 0.f;

    auto gload = [&](int k0) {
#pragma unroll
        for (int p = 0; p < 2; p++) {
            float4 u = *(const float4*)(pa[p] + k0);
            float4 v = *(const float4*)(pb[p] + k0);
            ra[p] = make_float4(gelu_f(u.x + v.x), gelu_f(u.y + v.y),
                                gelu_f(u.z + v.z), gelu_f(u.w + v.w));
        }
#pragma unroll
        for (int p = 0; p < 2; p++) {
            int kr = (t >> 5) + p*8, n4 = (t & 31) * 4;
            rb[p] = *(const float4*)(W + (size_t)(k0 + kr) * D_ + bn*128 + n4);
        }
    };
    auto sstore = [&](int buf) {
#pragma unroll
        for (int p = 0; p < 2; p++) {
            int r = aRow + p*64;
            As[buf][aK4+0][r] = to_tf32(ra[p].x);
            As[buf][aK4+1][r] = to_tf32(ra[p].y);
            As[buf][aK4+2][r] = to_tf32(ra[p].z);
            As[buf][aK4+3][r] = to_tf32(ra[p].w);
        }
#pragma unroll
        for (int p = 0; p < 2; p++) {
            int kr = (t >> 5) + p*8, n4 = (t & 31) * 4;
            Bs[buf][kr][n4+0] = to_tf32(rb[p].x);
            Bs[buf][kr][n4+1] = to_tf32(rb[p].y);
            Bs[buf][kr][n4+2] = to_tf32(rb[p].z);
            Bs[buf][kr][n4+3] = to_tf32(rb[p].w);
        }
    };
    auto compute = [&](int buf) {
#pragma unroll
        for (int kk = 0; kk < 16; kk += 8) {
            uint32_t af[4][4], bf[4][2];
#pragma unroll
            for (int mt = 0; mt < 4; mt++) {
                int m = warpM*64 + mt*16 + g;
                af[mt][0] = __float_as_uint(As[buf][kk+tg  ][m]);
                af[mt][1] = __float_as_uint(As[buf][kk+tg  ][m+8]);
                af[mt][2] = __float_as_uint(As[buf][kk+tg+4][m]);
                af[mt][3] = __float_as_uint(As[buf][kk+tg+4][m+8]);
            }
#pragma unroll
            for (int nt = 0; nt < 4; nt++) {
                int n = warpN*32 + nt*8 + g;
                bf[nt][0] = __float_as_uint(Bs[buf][kk+tg  ][n]);
                bf[nt][1] = __float_as_uint(Bs[buf][kk+tg+4][n]);
            }
#pragma unroll
            for (int mt = 0; mt < 4; mt++)
#pragma unroll
                for (int nt = 0; nt < 4; nt++) mma8(acc[mt][nt], af[mt], bf[nt]);
        }
    };

    const int nT = D_ >> 4;   // 48
    gload(0); sstore(0); __syncthreads();
    int buf = 0;
    for (int ti = 0; ti < nT; ++ti) {
        if (ti + 1 < nT) gload((ti + 1) << 4);
        compute(buf);
        if (ti + 1 < nT) sstore(buf ^ 1);
        __syncthreads();
        buf ^= 1;
    }
#pragma unroll
    for (int mt = 0; mt < 4; mt++)
#pragma unroll
        for (int nt = 0; nt < 4; nt++) {
            int row = bm*128 + warpM*64 + mt*16 + g;
            int col = bn*128 + warpN*32 + nt*8 + 2*tg;
            float b0 = bias[col], b1 = bias[col+1];
            *(float2*)(C + (size_t)row * N + col) =
                make_float2(acc[mt][nt][0] + b0, acc[mt][nt][1] + b1);
            *(float2*)(C + (size_t)(row + 8) * N + col) =
                make_float2(acc[mt][nt][2] + b0, acc[mt][nt][3] + b1);
        }
}

// ---------------- row LayerNorm (width 768) ----------------
__launch_bounds__(256)
__global__ void ln_kernel(const float* __restrict__ x, const float* __restrict__ g,
                          const float* __restrict__ b, float* __restrict__ out) {
    const int r = blockIdx.x, t = threadIdx.x;
    __shared__ float rs[8], rq[8], stat[2];
    const float* row = x + (size_t)r * D_;
    float v0 = row[t], v1 = row[t + 256], v2 = row[t + 512];
    float s = v0 + v1 + v2;
    float q = v0*v0 + v1*v1 + v2*v2;
#pragma unroll
    for (int o = 16; o > 0; o >>= 1) {
        s += __shfl_xor_sync(0xffffffffu, s, o);
        q += __shfl_xor_sync(0xffffffffu, q, o);
    }
    if ((t & 31) == 0) { rs[t >> 5] = s; rq[t >> 5] = q; }
    __syncthreads();
    if (t == 0) {
        float S = 0.f, Q = 0.f;
        for (int w = 0; w < 8; w++) { S += rs[w]; Q += rq[w]; }
        float mean = S * (1.f/768.f);
        float var  = Q * (1.f/768.f) - mean*mean;
        stat[0] = mean; stat[1] = rsqrtf(var + 1e-5f);
    }
    __syncthreads();
    float mean = stat[0], rstd = stat[1];
    float* o = out + (size_t)r * D_;
    o[t]       = (v0 - mean) * rstd * g[t]       + b[t];
    o[t + 256] = (v1 - mean) * rstd * g[t + 256] + b[t + 256];
    o[t + 512] = (v2 - mean) * rstd * g[t + 512] + b[t + 512];
}

// ---------------- softmax over rows of 1024 (in place) ----------------
__launch_bounds__(256)
__global__ void softmax_k(float* __restrict__ sc) {
    const int r = blockIdx.x, t = threadIdx.x;
    float* row = sc + (size_t)r * 1024;
    __shared__ float red[8], stat[1];
    float v0 = row[t], v1 = row[t+256], v2 = row[t+512], v3 = row[t+768];
    float m = fmaxf(fmaxf(v0, v1), fmaxf(v2, v3));
#pragma unroll
    for (int o = 16; o > 0; o >>= 1) m = fmaxf(m, __shfl_xor_sync(0xffffffffu, m, o));
    if ((t & 31) == 0) red[t >> 5] = m;
    __syncthreads();
    if (t == 0) {
        float M = red[0];
        for (int w = 1; w < 8; w++) M = fmaxf(M, red[w]);
        stat[0] = M;
    }
    __syncthreads();
    float M = stat[0];
    v0 = expf(v0 - M); v1 = expf(v1 - M); v2 = expf(v2 - M); v3 = expf(v3 - M);
    float s = v0 + v1 + v2 + v3;
#pragma unroll
    for (int o = 16; o > 0; o >>= 1) s += __shfl_xor_sync(0xffffffffu, s, o);
    __syncthreads();
    if ((t & 31) == 0) red[t >> 5] = s;
    __syncthreads();
    if (t == 0) {
        float S = 0.f;
        for (int w = 0; w < 8; w++) S += red[w];
        stat[0] = 1.f / S;
    }
    __syncthreads();
    float inv = stat[0];
    row[t] = v0*inv; row[t+256] = v1*inv; row[t+512] = v2*inv; row[t+768] = v3*inv;
}

// ---------------- per-(b,c,i): LN rows of Hp, mean over j, residual ----------
__launch_bounds__(256)
__global__ void relreduce(const float* __restrict__ Hp, const float* __restrict__ g,
                          const float* __restrict__ bln, const float* __restrict__ x1,
                          float* __restrict__ x2) {
    const int bci = blockIdx.x;
    const int t = threadIdx.x;
    __shared__ float rs[8], rq[8], stat[2];
    float a0 = 0.f, a1 = 0.f, a2 = 0.f;
    const float* base = Hp + (size_t)bci * 64 * D_;
    for (int j = 0; j < 64; j++) {
        const float* row = base + (size_t)j * D_;
        float v0 = row[t], v1 = row[t + 256], v2 = row[t + 512];
        float s = v0 + v1 + v2;
        float q = v0*v0 + v1*v1 + v2*v2;
#pragma unroll
        for (int o = 16; o > 0; o >>= 1) {
            s += __shfl_xor_sync(0xffffffffu, s, o);
            q += __shfl_xor_sync(0xffffffffu, q, o);
        }
        if ((t & 31) == 0) { rs[t >> 5] = s; rq[t >> 5] = q; }
        __syncthreads();
        if (t == 0) {
            float S = 0.f, Q = 0.f;
            for (int w = 0; w < 8; w++) { S += rs[w]; Q += rq[w]; }
            float mean = S * (1.f/768.f);
            float var  = Q * (1.f/768.f) - mean*mean;
            stat[0] = mean; stat[1] = rsqrtf(var + 1e-5f);
        }
        __syncthreads();
        float mean = stat[0], rstd = stat[1];
        a0 += (v0 - mean) * rstd;
        a1 += (v1 - mean) * rstd;
        a2 += (v2 - mean) * rstd;
        __syncthreads();
    }
    size_t o = (size_t)bci * D_;
    x2[o + t]       = x1[o + t]       + a0 * (1.f/64.f) * g[t]       + bln[t];
    x2[o + t + 256] = x1[o + t + 256] + a1 * (1.f/64.f) * g[t + 256] + bln[t + 256];
    x2[o + t + 512] = x1[o + t + 512] + a2 * (1.f/64.f) * g[t + 512] + bln[t + 512];
}

// ---------------- host orchestration ----------------
static float *P_h, *P_q, *P_k, *P_v, *P_ctx, *P_x1, *P_A, *P_Bm, *P_x2, *P_f, *P_Hp;
static bool g_init = false;

extern "C" void kernel_launch(void* const* d_in, const int* in_sizes, int n_in,
                              void* d_out, int out_size) {
    if (!g_init) {
        cudaGetSymbolAddress((void**)&P_h,   g_h);
        cudaGetSymbolAddress((void**)&P_q,   g_q);
        cudaGetSymbolAddress((void**)&P_k,   g_k);
        cudaGetSymbolAddress((void**)&P_v,   g_v);
        cudaGetSymbolAddress((void**)&P_ctx, g_ctx);
        cudaGetSymbolAddress((void**)&P_x1,  g_x1);
        cudaGetSymbolAddress((void**)&P_A,   g_A);
        cudaGetSymbolAddress((void**)&P_Bm,  g_Bm);
        cudaGetSymbolAddress((void**)&P_x2,  g_x2);
        cudaGetSymbolAddress((void**)&P_f,   g_f);
        cudaGetSymbolAddress((void**)&P_Hp,  g_Hp);
        g_init = true;
    }
    const float* x      = (const float*)d_in[0];
    const float* Wq     = (const float*)d_in[1];
    const float* bq     = (const float*)d_in[2];
    const float* Wk     = (const float*)d_in[3];
    const float* bk     = (const float*)d_in[4];
    const float* Wv     = (const float*)d_in[5];
    const float* bv     = (const float*)d_in[6];
    const float* Wo     = (const float*)d_in[7];
    const float* bo     = (const float*)d_in[8];
    const float* ln1_g  = (const float*)d_in[9];
    const float* ln1_b  = (const float*)d_in[10];
    const float* rel_W1 = (const float*)d_in[11];
    const float* rel_b1 = (const float*)d_in[12];
    const float* rel_W2 = (const float*)d_in[13];
    const float* rel_b2 = (const float*)d_in[14];
    const float* rel_ln_g = (const float*)d_in[15];
    const float* rel_ln_b = (const float*)d_in[16];
    const float* ln2_g  = (const float*)d_in[17];
    const float* ln2_b  = (const float*)d_in[18];
    const float* enc_W1 = (const float*)d_in[19];
    const float* enc_b1 = (const float*)d_in[20];
    const float* enc_W2 = (const float*)d_in[21];
    const float* enc_b2 = (const float*)d_in[22];
    float* out = (float*)d_out;

    const long long SD = (long long)S_ * D_;
    const long long SS = (long long)S_ * S_;

    // 1) h = LN1(x)
    ln_kernel<<<BS_, 256>>>(x, ln1_g, ln1_b, P_h);
    // 2) q,k,v projections
    dim3 gproj(6, 16, 1);
    gemm_tc<1,false><<<gproj, 256>>>(P_h, Wq, bq, nullptr, P_q, BS_, D_, D_,
                                     D_, D_, D_, 0,0,0,0,0,0);
    gemm_tc<1,false><<<gproj, 256>>>(P_h, Wk, bk, nullptr, P_k, BS_, D_, D_,
                                     D_, D_, D_, 0,0,0,0,0,0);
    gemm_tc<1,false><<<gproj, 256>>>(P_h, Wv, bv, nullptr, P_v, BS_, D_, D_,
                                     D_, D_, D_, 0,0,0,0,0,0);
    // 3) attention: scores = (Q Kᵀ)/8 staged in g_Hp, softmax, ctx = P V
    gemm_tc<4,true><<<dim3(8, 8, B_*H_), 256>>>(P_q, P_k, nullptr, nullptr, P_Hp,
                                     S_, S_, 64, D_, D_, S_,
                                     SD, 64, SD, 64, (long long)H_*SS, SS);
    softmax_k<<<B_*H_*S_, 256>>>(P_Hp);
    gemm_tc<0,false><<<dim3(1, 8, B_*H_), 256>>>(P_Hp, P_v, nullptr, nullptr, P_ctx,
                                     S_, 64, S_, S_, D_, D_,
                                     (long long)H_*SS, SS, SD, 64, SD, 64);
    // 4) x1 = x + ctx@Wo + bo
    gemm_tc<3,false><<<gproj, 256>>>(P_ctx, Wo, bo, x, P_x1, BS_, D_, D_,
                                     D_, D_, D_, 0,0,0,0,0,0);
    // 5) A = x1@W1a + b1 ;  Bm = x1@W1b
    gemm_tc<1,false><<<gproj, 256>>>(P_x1, rel_W1, rel_b1, nullptr, P_A, BS_, D_, D_,
                                     D_, D_, D_, 0,0,0,0,0,0);
    gemm_tc<0,false><<<gproj, 256>>>(P_x1, rel_W1 + D_*D_, nullptr, nullptr, P_Bm,
                                     BS_, D_, D_, D_, D_, D_, 0,0,0,0,0,0);
    // 6) relation pairwise GEMM + LN/mean reduction
    relgemm_tc<<<dim3(6, MREL/128), 256>>>(P_A, P_Bm, rel_W2, rel_b2, P_Hp);
    relreduce<<<BS_, 256>>>(P_Hp, rel_ln_g, rel_ln_b, P_x1, P_x2);
    // 7) FFN
    ln_kernel<<<BS_, 256>>>(P_x2, ln2_g, ln2_b, P_h);
    gemm_tc<2,false><<<dim3(24, 16, 1), 256>>>(P_h, enc_W1, enc_b1, nullptr, P_f,
                                     BS_, DFF_, D_, D_, DFF_, DFF_, 0,0,0,0,0,0);
    gemm_tc<3,false><<<gproj, 256>>>(P_f, enc_W2, enc_b2, P_x2, out, BS_, D_, DFF_,
                                     DFF_, D_, D_, 0,0,0,0,0,0);
}

// round 3
// speedup vs baseline: 2.5562x; 1.2321x over previous
#include <cuda_runtime.h>
#include <math.h>
#include <stdint.h>

#define B_   2
#define S_   1024
#define D_   768
#define H_   12
#define DFF_ 3072
#define BS_  2048
#define MREL 131072
#define STAGES 4

// ---------------- scratch ----------------
__device__ float g_h  [BS_*D_];
__device__ float g_q  [BS_*D_];
__device__ float g_k  [BS_*D_];
__device__ float g_v  [BS_*D_];
__device__ float g_ctx[BS_*D_];
__device__ float g_x1 [BS_*D_];
__device__ float g_A  [BS_*D_];
__device__ float g_Bm [BS_*D_];
__device__ float g_x2 [BS_*D_];
__device__ float g_f  [BS_*DFF_];
__device__ float g_Hp [(size_t)MREL*D_];   // relation out; reused for attn scores

__device__ __forceinline__ float gelu_f(float x) {
    return 0.5f * x * (1.0f + erff(x * 0.70710678118654752f));
}
__device__ __forceinline__ float to_tf32(float x) {
    uint32_t u; asm("cvt.rna.tf32.f32 %0, %1;" : "=r"(u) : "f"(x));
    return __uint_as_float(u);
}
__device__ __forceinline__ void mma8(float* c, const uint32_t* a, const uint32_t* b) {
    asm volatile(
        "mma.sync.aligned.m16n8k8.row.col.f32.tf32.tf32.f32 "
        "{%0,%1,%2,%3},{%4,%5,%6,%7},{%8,%9},{%0,%1,%2,%3};\n"
        : "+f"(c[0]), "+f"(c[1]), "+f"(c[2]), "+f"(c[3])
        : "r"(a[0]), "r"(a[1]), "r"(a[2]), "r"(a[3]), "r"(b[0]), "r"(b[1]));
}
__device__ __forceinline__ uint32_t smem_u32(const void* p) {
    return (uint32_t)__cvta_generic_to_shared(p);
}
__device__ __forceinline__ void cp16(uint32_t dst, const void* src, bool pred) {
    int sz = pred ? 16 : 0;
    asm volatile("cp.async.cg.shared.global [%0], [%1], 16, %2;\n"
                 :: "r"(dst), "l"(src), "r"(sz));
}
#define CP_COMMIT() asm volatile("cp.async.commit_group;\n")
#define CP_WAIT(n)  asm volatile("cp.async.wait_group %0;\n" :: "n"(n))

// EPI: 0=none 1=bias 2=bias+gelu 3=bias+res 4=*0.125
template<int EPI>
__device__ __forceinline__ void epi2(float* C, int ldc, const float* bias,
                                     const float* res, int row, int col,
                                     float v0, float v1) {
    if (EPI == 1 || EPI == 2 || EPI == 3) { v0 += bias[col]; v1 += bias[col+1]; }
    if (EPI == 2) { v0 = gelu_f(v0); v1 = gelu_f(v1); }
    if (EPI == 3) { size_t o = (size_t)row*ldc + col; v0 += res[o]; v1 += res[o+1]; }
    if (EPI == 4) { v0 *= 0.125f; v1 *= 0.125f; }
    *(float2*)(C + (size_t)row*ldc + col) = make_float2(v0, v1);
}

// ========== generic tf32 GEMM, 4-stage cp.async, BM=BN=128, BK=16 ==========
// smem: A [STAGES][128][20]  row-major [m][k];  B nontrans [STAGES][16][136],
// B trans [STAGES][128][20] ([n][k]).
template<int EPI, bool BTRANS>
__global__ void __launch_bounds__(256, 2)
gemm_tc(const float* __restrict__ A, const float* __restrict__ Bm_,
        const float* __restrict__ bias, const float* __restrict__ res,
        float* __restrict__ C, int M, int N, int K,
        int lda, int ldb, int ldc,
        long long aSB, long long aSH, long long bSB, long long bSH,
        long long cSB, long long cSH) {
    extern __shared__ float sm[];
    constexpr int ASZ = 128*20;
    constexpr int BSZ = BTRANS ? 128*20 : 16*136;
    float* Asm = sm;
    float* Bsm = sm + STAGES*ASZ;

    const int t = threadIdx.x, bm = blockIdx.y, bn = blockIdx.x, z = blockIdx.z;
    A   += (z / H_) * aSB + (z % H_) * aSH;
    Bm_ += (z / H_) * bSB + (z % H_) * bSH;
    C   += (z / H_) * cSB + (z % H_) * cSH;
    if (EPI == 3) res += (z / H_) * cSB + (z % H_) * cSH;
    const int lane = t & 31, wid = t >> 5;
    const int warpM = wid & 1, warpN = wid >> 1;
    const int g = lane >> 2, tg = lane & 3;

    // copy geometry
    const int ar = t >> 2, akq = (t & 3) * 4;       // A chunks: rows ar, ar+64
    const int bkr = t >> 5, bn4 = (t & 31) * 4;     // B nontrans: krows bkr, bkr+8

    const float* Ab0 = A + (size_t)(bm*128) * lda;

    auto issueA = [&](int s, int k0) {
        float* dst = Asm + s*ASZ;
        cp16(smem_u32(dst + ar*20 + akq),      Ab0 + (size_t)ar*lda + k0 + akq, true);
        cp16(smem_u32(dst + (ar+64)*20 + akq), Ab0 + (size_t)(ar+64)*lda + k0 + akq, true);
    };
    auto issueB = [&](int s, int k0) {
        float* dst = Bsm + s*BSZ;
        if (!BTRANS) {
            bool p = (bn*128 + bn4) < N;
            cp16(smem_u32(dst + bkr*136 + bn4),
                 Bm_ + (size_t)(k0 + bkr)*ldb + bn*128 + bn4, p);
            cp16(smem_u32(dst + (bkr+8)*136 + bn4),
                 Bm_ + (size_t)(k0 + bkr + 8)*ldb + bn*128 + bn4, p);
        } else {
            bool p0 = (bn*128 + ar) < N, p1 = (bn*128 + ar + 64) < N;
            cp16(smem_u32(dst + ar*20 + akq),
                 Bm_ + (size_t)(bn*128 + ar)*ldb + k0 + akq, p0);
            cp16(smem_u32(dst + (ar+64)*20 + akq),
                 Bm_ + (size_t)(bn*128 + ar + 64)*ldb + k0 + akq, p1);
        }
    };

    float acc[4][4][4];
#pragma unroll
    for (int i = 0; i < 4; i++)
#pragma unroll
        for (int j = 0; j < 4; j++)
#pragma unroll
            for (int c = 0; c < 4; c++) acc[i][j][c] = 0.f;

    auto compute = [&](int s) {
        const float* Ab = Asm + s*ASZ;
        const float* Bb = Bsm + s*BSZ;
#pragma unroll
        for (int kk = 0; kk < 16; kk += 8) {
            uint32_t af[4][4], bf[4][2];
#pragma unroll
            for (int mt = 0; mt < 4; mt++) {
                int m = warpM*64 + mt*16 + g;
                af[mt][0] = __float_as_uint(Ab[m*20     + kk+tg]);
                af[mt][1] = __float_as_uint(Ab[(m+8)*20 + kk+tg]);
                af[mt][2] = __float_as_uint(Ab[m*20     + kk+tg+4]);
                af[mt][3] = __float_as_uint(Ab[(m+8)*20 + kk+tg+4]);
            }
#pragma unroll
            for (int nt = 0; nt < 4; nt++) {
                int n = warpN*32 + nt*8 + g;
                if (!BTRANS) {
                    bf[nt][0] = __float_as_uint(Bb[(kk+tg)*136   + n]);
                    bf[nt][1] = __float_as_uint(Bb[(kk+tg+4)*136 + n]);
                } else {
                    bf[nt][0] = __float_as_uint(Bb[n*20 + kk+tg]);
                    bf[nt][1] = __float_as_uint(Bb[n*20 + kk+tg+4]);
                }
            }
#pragma unroll
            for (int mt = 0; mt < 4; mt++)
#pragma unroll
                for (int nt = 0; nt < 4; nt++) mma8(acc[mt][nt], af[mt], bf[nt]);
        }
    };

    const int nT = K >> 4;
#pragma unroll
    for (int s = 0; s < STAGES-1; s++) {
        if (s < nT) { issueA(s, s*16); issueB(s, s*16); }
        CP_COMMIT();
    }
    for (int ti = 0; ti < nT; ti++) {
        CP_WAIT(STAGES-2);
        __syncthreads();
        int nx = ti + STAGES - 1;
        if (nx < nT) { issueA(nx % STAGES, nx*16); issueB(nx % STAGES, nx*16); }
        CP_COMMIT();
        compute(ti % STAGES);
    }
#pragma unroll
    for (int mt = 0; mt < 4; mt++)
#pragma unroll
        for (int nt = 0; nt < 4; nt++) {
            int row = bm*128 + warpM*64 + mt*16 + g;
            int col = bn*128 + warpN*32 + nt*8 + 2*tg;
            if (col < N) {
                epi2<EPI>(C, ldc, bias, res, row,     col, acc[mt][nt][0], acc[mt][nt][1]);
                epi2<EPI>(C, ldc, bias, res, row + 8, col, acc[mt][nt][2], acc[mt][nt][3]);
            }
        }
}

// ====== relation GEMM: virtual rows gelu(Ar[i]+Br[j]) @ W2[768x768] + b ======
// A: 2-stage register->smem buffer (gelu computed in regs, rna-rounded)
// B: 4-stage cp.async
__global__ void __launch_bounds__(256, 2)
relgemm_tc(const float* __restrict__ Ar, const float* __restrict__ Br,
           const float* __restrict__ W, const float* __restrict__ bias,
           float* __restrict__ C) {
    extern __shared__ float sm[];
    constexpr int ASZ = 128*20;
    constexpr int BSZ = 16*136;
    float* Asm = sm;                 // [2][ASZ]
    float* Bsm = sm + 2*ASZ;         // [STAGES][BSZ]

    const int t = threadIdx.x, bm = blockIdx.y, bn = blockIdx.x;
    const int lane = t & 31, wid = t >> 5;
    const int warpM = wid & 1, warpN = wid >> 1;
    const int g = lane >> 2, tg = lane & 3;
    const int r0 = t >> 2, akq = (t & 3) * 4;
    const int r1 = r0 + 64;
    const int bkr = t >> 5, bn4 = (t & 31) * 4;

    const float* pa0; const float* pb0; const float* pa1; const float* pb1;
    {
        int m0 = bm*128 + r0, m1 = bm*128 + r1;
        int cb0 = (m0 >> 12) << 6, cb1 = (m1 >> 12) << 6;
        pa0 = Ar + (size_t)(cb0 + ((m0 >> 6) & 63)) * D_ + akq;
        pb0 = Br + (size_t)(cb0 + (m0 & 63)) * D_ + akq;
        pa1 = Ar + (size_t)(cb1 + ((m1 >> 6) & 63)) * D_ + akq;
        pb1 = Br + (size_t)(cb1 + (m1 & 63)) * D_ + akq;
    }

    float4 ua, va, ub, vb;
    auto loadA = [&](int k0) {
        ua = *(const float4*)(pa0 + k0); va = *(const float4*)(pb0 + k0);
        ub = *(const float4*)(pa1 + k0); vb = *(const float4*)(pb1 + k0);
    };
    auto storeA = [&](int s) {
        float* dst = Asm + s*ASZ;
        dst[r0*20 + akq+0] = to_tf32(gelu_f(ua.x + va.x));
        dst[r0*20 + akq+1] = to_tf32(gelu_f(ua.y + va.y));
        dst[r0*20 + akq+2] = to_tf32(gelu_f(ua.z + va.z));
        dst[r0*20 + akq+3] = to_tf32(gelu_f(ua.w + va.w));
        dst[r1*20 + akq+0] = to_tf32(gelu_f(ub.x + vb.x));
        dst[r1*20 + akq+1] = to_tf32(gelu_f(ub.y + vb.y));
        dst[r1*20 + akq+2] = to_tf32(gelu_f(ub.z + vb.z));
        dst[r1*20 + akq+3] = to_tf32(gelu_f(ub.w + vb.w));
    };
    auto issueB = [&](int s, int k0) {
        float* dst = Bsm + s*BSZ;
        cp16(smem_u32(dst + bkr*136 + bn4),
             W + (size_t)(k0 + bkr)*D_ + bn*128 + bn4, true);
        cp16(smem_u32(dst + (bkr+8)*136 + bn4),
             W + (size_t)(k0 + bkr + 8)*D_ + bn*128 + bn4, true);
    };

    float acc[4][4][4];
#pragma unroll
    for (int i = 0; i < 4; i++)
#pragma unroll
        for (int j = 0; j < 4; j++)
#pragma unroll
            for (int c = 0; c < 4; c++) acc[i][j][c] = 0.f;

    auto compute = [&](int sA, int sB) {
        const float* Ab = Asm + sA*ASZ;
        const float* Bb = Bsm + sB*BSZ;
#pragma unroll
        for (int kk = 0; kk < 16; kk += 8) {
            uint32_t af[4][4], bf[4][2];
#pragma unroll
            for (int mt = 0; mt < 4; mt++) {
                int m = warpM*64 + mt*16 + g;
                af[mt][0] = __float_as_uint(Ab[m*20     + kk+tg]);
                af[mt][1] = __float_as_uint(Ab[(m+8)*20 + kk+tg]);
                af[mt][2] = __float_as_uint(Ab[m*20     + kk+tg+4]);
                af[mt][3] = __float_as_uint(Ab[(m+8)*20 + kk+tg+4]);
            }
#pragma unroll
            for (int nt = 0; nt < 4; nt++) {
                int n = warpN*32 + nt*8 + g;
                bf[nt][0] = __float_as_uint(Bb[(kk+tg)*136   + n]);
                bf[nt][1] = __float_as_uint(Bb[(kk+tg+4)*136 + n]);
            }
#pragma unroll
            for (int mt = 0; mt < 4; mt++)
#pragma unroll
                for (int nt = 0; nt < 4; nt++) mma8(acc[mt][nt], af[mt], bf[nt]);
        }
    };

    const int nT = D_ >> 4;   // 48
#pragma unroll
    for (int s = 0; s < STAGES-1; s++) { issueB(s, s*16); CP_COMMIT(); }
    loadA(0); storeA(0);
    for (int ti = 0; ti < nT; ti++) {
        if (ti + 1 < nT) loadA((ti+1)*16);
        CP_WAIT(STAGES-2);
        __syncthreads();
        int nx = ti + STAGES - 1;
        if (nx < nT) issueB(nx % STAGES, nx*16);
        CP_COMMIT();
        compute(ti & 1, ti % STAGES);
        if (ti + 1 < nT) storeA((ti+1) & 1);
    }
#pragma unroll
    for (int mt = 0; mt < 4; mt++)
#pragma unroll
        for (int nt = 0; nt < 4; nt++) {
            int row = bm*128 + warpM*64 + mt*16 + g;
            int col = bn*128 + warpN*32 + nt*8 + 2*tg;
            float b0 = bias[col], b1 = bias[col+1];
            *(float2*)(C + (size_t)row * D_ + col) =
                make_float2(acc[mt][nt][0] + b0, acc[mt][nt][1] + b1);
            *(float2*)(C + (size_t)(row + 8) * D_ + col) =
                make_float2(acc[mt][nt][2] + b0, acc[mt][nt][3] + b1);
        }
}

// ---------------- row LayerNorm (width 768) ----------------
__launch_bounds__(256)
__global__ void ln_kernel(const float* __restrict__ x, const float* __restrict__ g,
                          const float* __restrict__ b, float* __restrict__ out) {
    const int r = blockIdx.x, t = threadIdx.x;
    __shared__ float rs[8], rq[8], stat[2];
    const float* row = x + (size_t)r * D_;
    float v0 = row[t], v1 = row[t + 256], v2 = row[t + 512];
    float s = v0 + v1 + v2;
    float q = v0*v0 + v1*v1 + v2*v2;
#pragma unroll
    for (int o = 16; o > 0; o >>= 1) {
        s += __shfl_xor_sync(0xffffffffu, s, o);
        q += __shfl_xor_sync(0xffffffffu, q, o);
    }
    if ((t & 31) == 0) { rs[t >> 5] = s; rq[t >> 5] = q; }
    __syncthreads();
    if (t == 0) {
        float S = 0.f, Q = 0.f;
        for (int w = 0; w < 8; w++) { S += rs[w]; Q += rq[w]; }
        float mean = S * (1.f/768.f);
        float var  = Q * (1.f/768.f) - mean*mean;
        stat[0] = mean; stat[1] = rsqrtf(var + 1e-5f);
    }
    __syncthreads();
    float mean = stat[0], rstd = stat[1];
    float* o = out + (size_t)r * D_;
    o[t]       = (v0 - mean) * rstd * g[t]       + b[t];
    o[t + 256] = (v1 - mean) * rstd * g[t + 256] + b[t + 256];
    o[t + 512] = (v2 - mean) * rstd * g[t + 512] + b[t + 512];
}

// ---------------- softmax over rows of 1024 (in place) ----------------
__launch_bounds__(256)
__global__ void softmax_k(float* __restrict__ sc) {
    const int r = blockIdx.x, t = threadIdx.x;
    float* row = sc + (size_t)r * 1024;
    __shared__ float red[8], stat[1];
    float v0 = row[t], v1 = row[t+256], v2 = row[t+512], v3 = row[t+768];
    float m = fmaxf(fmaxf(v0, v1), fmaxf(v2, v3));
#pragma unroll
    for (int o = 16; o > 0; o >>= 1) m = fmaxf(m, __shfl_xor_sync(0xffffffffu, m, o));
    if ((t & 31) == 0) red[t >> 5] = m;
    __syncthreads();
    if (t == 0) {
        float M = red[0];
        for (int w = 1; w < 8; w++) M = fmaxf(M, red[w]);
        stat[0] = M;
    }
    __syncthreads();
    float M = stat[0];
    v0 = expf(v0 - M); v1 = expf(v1 - M); v2 = expf(v2 - M); v3 = expf(v3 - M);
    float s = v0 + v1 + v2 + v3;
#pragma unroll
    for (int o = 16; o > 0; o >>= 1) s += __shfl_xor_sync(0xffffffffu, s, o);
    __syncthreads();
    if ((t & 31) == 0) red[t >> 5] = s;
    __syncthreads();
    if (t == 0) {
        float S = 0.f;
        for (int w = 0; w < 8; w++) S += red[w];
        stat[0] = 1.f / S;
    }
    __syncthreads();
    float inv = stat[0];
    row[t] = v0*inv; row[t+256] = v1*inv; row[t+512] = v2*inv; row[t+768] = v3*inv;
}

// ---- relreduce v2: warp-per-j-row LN + mean over j + residual + fused LN2 ---
__launch_bounds__(256)
__global__ void relreduce(const float* __restrict__ Hp, const float* __restrict__ g,
                          const float* __restrict__ bln, const float* __restrict__ x1,
                          float* __restrict__ x2,
                          const float* __restrict__ ln2g, const float* __restrict__ ln2b,
                          float* __restrict__ hout) {
    const int bci = blockIdx.x, t = threadIdx.x;
    const int w = t >> 5, lane = t & 31;
    __shared__ float smacc[8][768];
    __shared__ float rs[8], rq[8], stat[2];

    float acc[24];
#pragma unroll
    for (int e = 0; e < 24; e++) acc[e] = 0.f;

    const float* base = Hp + (size_t)bci * 64 * D_;
    for (int jj = 0; jj < 8; jj++) {
        const float* row = base + (size_t)(w + jj*8) * D_;
        float v[24]; float s = 0.f, q = 0.f;
#pragma unroll
        for (int e = 0; e < 24; e++) {
            v[e] = row[lane + 32*e];
            s += v[e]; q += v[e]*v[e];
        }
#pragma unroll
        for (int o = 16; o > 0; o >>= 1) {
            s += __shfl_xor_sync(0xffffffffu, s, o);
            q += __shfl_xor_sync(0xffffffffu, q, o);
        }
        float mean = s * (1.f/768.f);
        float rstd = rsqrtf(q * (1.f/768.f) - mean*mean + 1e-5f);
#pragma unroll
        for (int e = 0; e < 24; e++) acc[e] += (v[e] - mean) * rstd;
    }
#pragma unroll
    for (int e = 0; e < 24; e++) smacc[w][lane + 32*e] = acc[e];
    __syncthreads();

    // outputs: thread t handles cols t, t+256, t+512
    float o0 = 0.f, o1 = 0.f, o2 = 0.f;
#pragma unroll
    for (int w8 = 0; w8 < 8; w8++) {
        o0 += smacc[w8][t];
        o1 += smacc[w8][t + 256];
        o2 += smacc[w8][t + 512];
    }
    size_t off = (size_t)bci * D_;
    o0 = x1[off + t]       + o0 * (1.f/64.f) * g[t]       + bln[t];
    o1 = x1[off + t + 256] + o1 * (1.f/64.f) * g[t + 256] + bln[t + 256];
    o2 = x1[off + t + 512] + o2 * (1.f/64.f) * g[t + 512] + bln[t + 512];
    x2[off + t] = o0; x2[off + t + 256] = o1; x2[off + t + 512] = o2;

    // fused LN2 -> hout
    float s = o0 + o1 + o2, q = o0*o0 + o1*o1 + o2*o2;
#pragma unroll
    for (int o = 16; o > 0; o >>= 1) {
        s += __shfl_xor_sync(0xffffffffu, s, o);
        q += __shfl_xor_sync(0xffffffffu, q, o);
    }
    if (lane == 0) { rs[w] = s; rq[w] = q; }
    __syncthreads();
    if (t == 0) {
        float S = 0.f, Q = 0.f;
        for (int w8 = 0; w8 < 8; w8++) { S += rs[w8]; Q += rq[w8]; }
        float mean = S * (1.f/768.f);
        float var  = Q * (1.f/768.f) - mean*mean;
        stat[0] = mean; stat[1] = rsqrtf(var + 1e-5f);
    }
    __syncthreads();
    float mean = stat[0], rstd = stat[1];
    hout[off + t]       = (o0 - mean) * rstd * ln2g[t]       + ln2b[t];
    hout[off + t + 256] = (o1 - mean) * rstd * ln2g[t + 256] + ln2b[t + 256];
    hout[off + t + 512] = (o2 - mean) * rstd * ln2g[t + 512] + ln2b[t + 512];
}

// ---------------- host orchestration ----------------
static float *P_h, *P_q, *P_k, *P_v, *P_ctx, *P_x1, *P_A, *P_Bm, *P_x2, *P_f, *P_Hp;
static bool g_init = false;

#define SM_NT  (STAGES*(128*20 + 16*136)*4)   // 75776
#define SM_T   (STAGES*(128*20 + 128*20)*4)   // 81920
#define SM_REL ((2*128*20 + STAGES*16*136)*4) // 55296

extern "C" void kernel_launch(void* const* d_in, const int* in_sizes, int n_in,
                              void* d_out, int out_size) {
    if (!g_init) {
        cudaGetSymbolAddress((void**)&P_h,   g_h);
        cudaGetSymbolAddress((void**)&P_q,   g_q);
        cudaGetSymbolAddress((void**)&P_k,   g_k);
        cudaGetSymbolAddress((void**)&P_v,   g_v);
        cudaGetSymbolAddress((void**)&P_ctx, g_ctx);
        cudaGetSymbolAddress((void**)&P_x1,  g_x1);
        cudaGetSymbolAddress((void**)&P_A,   g_A);
        cudaGetSymbolAddress((void**)&P_Bm,  g_Bm);
        cudaGetSymbolAddress((void**)&P_x2,  g_x2);
        cudaGetSymbolAddress((void**)&P_f,   g_f);
        cudaGetSymbolAddress((void**)&P_Hp,  g_Hp);
        cudaFuncSetAttribute(gemm_tc<1,false>, cudaFuncAttributeMaxDynamicSharedMemorySize, SM_NT);
        cudaFuncSetAttribute(gemm_tc<0,false>, cudaFuncAttributeMaxDynamicSharedMemorySize, SM_NT);
        cudaFuncSetAttribute(gemm_tc<2,false>, cudaFuncAttributeMaxDynamicSharedMemorySize, SM_NT);
        cudaFuncSetAttribute(gemm_tc<3,false>, cudaFuncAttributeMaxDynamicSharedMemorySize, SM_NT);
        cudaFuncSetAttribute(gemm_tc<4,true>,  cudaFuncAttributeMaxDynamicSharedMemorySize, SM_T);
        cudaFuncSetAttribute(relgemm_tc,       cudaFuncAttributeMaxDynamicSharedMemorySize, SM_REL);
        g_init = true;
    }
    const float* x      = (const float*)d_in[0];
    const float* Wq     = (const float*)d_in[1];
    const float* bq     = (const float*)d_in[2];
    const float* Wk     = (const float*)d_in[3];
    const float* bk     = (const float*)d_in[4];
    const float* Wv     = (const float*)d_in[5];
    const float* bv     = (const float*)d_in[6];
    const float* Wo     = (const float*)d_in[7];
    const float* bo     = (const float*)d_in[8];
    const float* ln1_g  = (const float*)d_in[9];
    const float* ln1_b  = (const float*)d_in[10];
    const float* rel_W1 = (const float*)d_in[11];
    const float* rel_b1 = (const float*)d_in[12];
    const float* rel_W2 = (const float*)d_in[13];
    const float* rel_b2 = (const float*)d_in[14];
    const float* rel_ln_g = (const float*)d_in[15];
    const float* rel_ln_b = (const float*)d_in[16];
    const float* ln2_g  = (const float*)d_in[17];
    const float* ln2_b  = (const float*)d_in[18];
    const float* enc_W1 = (const float*)d_in[19];
    const float* enc_b1 = (const float*)d_in[20];
    const float* enc_W2 = (const float*)d_in[21];
    const float* enc_b2 = (const float*)d_in[22];
    float* out = (float*)d_out;

    const long long SD = (long long)S_ * D_;
    const long long SS = (long long)S_ * S_;

    // 1) h = LN1(x)
    ln_kernel<<<BS_, 256>>>(x, ln1_g, ln1_b, P_h);
    // 2) q,k,v projections
    dim3 gproj(6, 16, 1);
    gemm_tc<1,false><<<gproj, 256, SM_NT>>>(P_h, Wq, bq, nullptr, P_q, BS_, D_, D_,
                                     D_, D_, D_, 0,0,0,0,0,0);
    gemm_tc<1,false><<<gproj, 256, SM_NT>>>(P_h, Wk, bk, nullptr, P_k, BS_, D_, D_,
                                     D_, D_, D_, 0,0,0,0,0,0);
    gemm_tc<1,false><<<gproj, 256, SM_NT>>>(P_h, Wv, bv, nullptr, P_v, BS_, D_, D_,
                                     D_, D_, D_, 0,0,0,0,0,0);
    // 3) attention
    gemm_tc<4,true><<<dim3(8, 8, B_*H_), 256, SM_T>>>(P_q, P_k, nullptr, nullptr, P_Hp,
                                     S_, S_, 64, D_, D_, S_,
                                     SD, 64, SD, 64, (long long)H_*SS, SS);
    softmax_k<<<B_*H_*S_, 256>>>(P_Hp);
    gemm_tc<0,false><<<dim3(1, 8, B_*H_), 256, SM_NT>>>(P_Hp, P_v, nullptr, nullptr, P_ctx,
                                     S_, 64, S_, S_, D_, D_,
                                     (long long)H_*SS, SS, SD, 64, SD, 64);
    // 4) x1 = x + ctx@Wo + bo
    gemm_tc<3,false><<<gproj, 256, SM_NT>>>(P_ctx, Wo, bo, x, P_x1, BS_, D_, D_,
                                     D_, D_, D_, 0,0,0,0,0,0);
    // 5) A = x1@W1a + b1 ;  Bm = x1@W1b
    gemm_tc<1,false><<<gproj, 256, SM_NT>>>(P_x1, rel_W1, rel_b1, nullptr, P_A, BS_, D_, D_,
                                     D_, D_, D_, 0,0,0,0,0,0);
    gemm_tc<0,false><<<gproj, 256, SM_NT>>>(P_x1, rel_W1 + D_*D_, nullptr, nullptr, P_Bm,
                                     BS_, D_, D_, D_, D_, D_, 0,0,0,0,0,0);
    // 6) relation pairwise GEMM + fused reduction (+LN2)
    relgemm_tc<<<dim3(6, MREL/128), 256, SM_REL>>>(P_A, P_Bm, rel_W2, rel_b2, P_Hp);
    relreduce<<<BS_, 256>>>(P_Hp, rel_ln_g, rel_ln_b, P_x1, P_x2, ln2_g, ln2_b, P_h);
    // 7) FFN
    gemm_tc<2,false><<<dim3(24, 16, 1), 256, SM_NT>>>(P_h, enc_W1, enc_b1, nullptr, P_f,
                                     BS_, DFF_, D_, D_, DFF_, DFF_, 0,0,0,0,0,0);
    gemm_tc<3,false><<<gproj, 256, SM_NT>>>(P_f, enc_W2, enc_b2, P_x2, out, BS_, D_, DFF_,
                                     DFF_, D_, D_, 0,0,0,0,0,0);
}

// round 4
// speedup vs baseline: 3.6870x; 1.4424x over previous
#include <cuda_runtime.h>
#include <cuda_fp16.h>
#include <math.h>
#include <stdint.h>

#define B_   2
#define S_   1024
#define D_   768
#define H_   12
#define DFF_ 3072
#define BS_  2048
#define MREL 131072
#define STAGES 4

// ---------------- scratch ----------------
__device__ float  g_x1 [BS_*D_];
__device__ float  g_A  [BS_*D_];
__device__ float  g_Bm [BS_*D_];
__device__ float  g_x2 [BS_*D_];
__device__ float  g_Hp [(size_t)MREL*D_];      // relation out fp32; attn scores fp32
__device__ __half g_hh [BS_*D_];               // ln1 out / ffn-LN out (fp16)
__device__ __half g_qh [BS_*D_];
__device__ __half g_kh [BS_*D_];
__device__ __half g_vh [BS_*D_];
__device__ __half g_ctxh[BS_*D_];
__device__ __half g_x1h[BS_*D_];
__device__ __half g_fh [BS_*DFF_];
__device__ __half g_ph [(size_t)B_*H_*S_*S_];  // softmax probs fp16 (50MB)
// fp16 weights
__device__ __half g_Wqh[D_*D_], g_Wkh[D_*D_], g_Wvh[D_*D_], g_Woh[D_*D_];
__device__ __half g_W1h[2*D_*D_], g_W2h[D_*D_];
__device__ __half g_E1h[D_*DFF_], g_E2h[DFF_*D_];

__device__ __forceinline__ float gelu_f(float x) {
    return 0.5f * x * (1.0f + erff(x * 0.70710678118654752f));
}
__device__ __forceinline__ uint32_t smem_u32(const void* p) {
    return (uint32_t)__cvta_generic_to_shared(p);
}
__device__ __forceinline__ void cp16(uint32_t dst, const void* src, bool pred) {
    int sz = pred ? 16 : 0;
    asm volatile("cp.async.cg.shared.global [%0], [%1], 16, %2;\n"
                 :: "r"(dst), "l"(src), "r"(sz));
}
#define CP_COMMIT() asm volatile("cp.async.commit_group;\n")
#define CP_WAIT(n)  asm volatile("cp.async.wait_group %0;\n" :: "n"(n))

__device__ __forceinline__ void ldm_x4(uint32_t* r, uint32_t a) {
    asm volatile("ldmatrix.sync.aligned.m8n8.x4.shared.b16 {%0,%1,%2,%3},[%4];"
                 : "=r"(r[0]), "=r"(r[1]), "=r"(r[2]), "=r"(r[3]) : "r"(a));
}
__device__ __forceinline__ void ldm_x2t(uint32_t* r, uint32_t a) {
    asm volatile("ldmatrix.sync.aligned.m8n8.x2.trans.shared.b16 {%0,%1},[%2];"
                 : "=r"(r[0]), "=r"(r[1]) : "r"(a));
}
__device__ __forceinline__ void ldm_x2(uint32_t* r, uint32_t a) {
    asm volatile("ldmatrix.sync.aligned.m8n8.x2.shared.b16 {%0,%1},[%2];"
                 : "=r"(r[0]), "=r"(r[1]) : "r"(a));
}
__device__ __forceinline__ void mma_h(float* c, const uint32_t* a, const uint32_t* b) {
    asm volatile(
        "mma.sync.aligned.m16n8k16.row.col.f32.f16.f16.f32 "
        "{%0,%1,%2,%3},{%4,%5,%6,%7},{%8,%9},{%0,%1,%2,%3};\n"
        : "+f"(c[0]), "+f"(c[1]), "+f"(c[2]), "+f"(c[3])
        : "r"(a[0]), "r"(a[1]), "r"(a[2]), "r"(a[3]), "r"(b[0]), "r"(b[1]));
}

// ---------------- fp32 -> fp16 conversion ----------------
__global__ void conv_h(const float* __restrict__ s, __half* __restrict__ d, int n) {
    int i = (blockIdx.x * 256 + threadIdx.x) * 4;
    if (i < n) {
        float4 v = *(const float4*)(s + i);
        __half2 a = __floats2half2_rn(v.x, v.y);
        __half2 b = __floats2half2_rn(v.z, v.w);
        *(uint2*)(d + i) = make_uint2(*(uint32_t*)&a, *(uint32_t*)&b);
    }
}

// smem geometry (halves): A tiles [128][24] (16 used + 8 pad); B_nt [16][136]; B_t [128][24]
#define A_ST  (128*24)
#define BNT_ST (16*136)
#define BT_ST (128*24)

// ========== generic fp16 GEMM, BM=BN=128, BK=16, 4-stage cp.async ==========
// EPI: 0=none 1=bias 2=bias+gelu 3=bias+res 4=*0.125
template<int EPI, bool BTRANS, bool O32, bool O16>
__global__ void __launch_bounds__(256, 2)
gemm_h(const __half* __restrict__ A, const __half* __restrict__ Bm_,
       const float* __restrict__ bias, const float* __restrict__ res,
       float* __restrict__ C32, __half* __restrict__ C16,
       int M, int N, int K, int lda, int ldb, int ldc,
       long long aSB, long long aSH, long long bSB, long long bSH,
       long long cSB, long long cSH) {
    extern __shared__ __align__(16) __half sm[];
    constexpr int BSZ = BTRANS ? BT_ST : BNT_ST;
    __half* Asm = sm;
    __half* Bsm = sm + STAGES*A_ST;

    const int t = threadIdx.x, bm = blockIdx.y, bn = blockIdx.x, z = blockIdx.z;
    A   += (z / H_) * aSB + (z % H_) * aSH;
    Bm_ += (z / H_) * bSB + (z % H_) * bSH;
    long long cOff = (z / H_) * cSB + (z % H_) * cSH;
    const int lane = t & 31, wid = t >> 5;
    const int warpM = wid & 1, warpN = wid >> 1;
    const int g = lane >> 2, tg = lane & 3;

    const int ar = t >> 1, akc = (t & 1) * 8;        // A copy: row ar, 8 halves
    const int bkr = t >> 4, bnc = (t & 15) * 8;      // B_nt copy

    const __half* Ab0 = A + (size_t)(bm*128) * lda;

    auto issueA = [&](int s, int k0) {
        __half* dst = Asm + s*A_ST;
        cp16(smem_u32(dst + ar*24 + akc), Ab0 + (size_t)ar*lda + k0 + akc, true);
    };
    auto issueB = [&](int s, int k0) {
        __half* dst = Bsm + s*BSZ;
        if (!BTRANS) {
            bool p = (bn*128 + bnc) < N;
            cp16(smem_u32(dst + bkr*136 + bnc),
                 Bm_ + (size_t)(k0 + bkr)*ldb + bn*128 + bnc, p);
        } else {
            bool p = (bn*128 + ar) < N;
            cp16(smem_u32(dst + ar*24 + akc),
                 Bm_ + (size_t)(bn*128 + ar)*ldb + k0 + akc, p);
        }
    };

    float acc[4][4][4];
#pragma unroll
    for (int i = 0; i < 4; i++)
#pragma unroll
        for (int j = 0; j < 4; j++)
#pragma unroll
            for (int c = 0; c < 4; c++) acc[i][j][c] = 0.f;

    const int l16 = lane & 15, lhi = lane >> 4;
    auto compute = [&](int s) {
        const __half* Ab = Asm + s*A_ST;
        const __half* Bb = Bsm + s*BSZ;
        uint32_t af[4][4], bf[4][2];
#pragma unroll
        for (int mt = 0; mt < 4; mt++) {
            int m0 = warpM*64 + mt*16;
            ldm_x4(af[mt], smem_u32(Ab + (m0 + l16)*24 + lhi*8));
        }
#pragma unroll
        for (int nt = 0; nt < 4; nt++) {
            int n0 = warpN*32 + nt*8;
            if (!BTRANS) ldm_x2t(bf[nt], smem_u32(Bb + l16*136 + n0));
            else         ldm_x2 (bf[nt], smem_u32(Bb + (n0 + (l16 & 7))*24 + (l16 >> 3)*8));
        }
#pragma unroll
        for (int mt = 0; mt < 4; mt++)
#pragma unroll
            for (int nt = 0; nt < 4; nt++) mma_h(acc[mt][nt], af[mt], bf[nt]);
    };

    const int nT = K >> 4;
#pragma unroll
    for (int s = 0; s < STAGES-1; s++) {
        if (s < nT) { issueA(s, s*16); issueB(s, s*16); }
        CP_COMMIT();
    }
    for (int ti = 0; ti < nT; ti++) {
        CP_WAIT(STAGES-2);
        __syncthreads();
        int nx = ti + STAGES - 1;
        if (nx < nT) { issueA(nx % STAGES, nx*16); issueB(nx % STAGES, nx*16); }
        CP_COMMIT();
        compute(ti % STAGES);
    }
#pragma unroll
    for (int mt = 0; mt < 4; mt++)
#pragma unroll
        for (int nt = 0; nt < 4; nt++) {
            int col = bn*128 + warpN*32 + nt*8 + 2*tg;
            if (col >= N) continue;
#pragma unroll
            for (int h = 0; h < 2; h++) {
                int row = bm*128 + warpM*64 + mt*16 + g + h*8;
                float v0 = acc[mt][nt][2*h], v1 = acc[mt][nt][2*h+1];
                if (EPI == 1 || EPI == 2 || EPI == 3) { v0 += bias[col]; v1 += bias[col+1]; }
                if (EPI == 2) { v0 = gelu_f(v0); v1 = gelu_f(v1); }
                if (EPI == 3) { size_t o = (size_t)row*ldc + col; v0 += res[o]; v1 += res[o+1]; }
                if (EPI == 4) { v0 *= 0.125f; v1 *= 0.125f; }
                size_t o = cOff + (size_t)row*ldc + col;
                if (O32) *(float2*)(C32 + o) = make_float2(v0, v1);
                if (O16) *(__half2*)(C16 + o) = __floats2half2_rn(v0, v1);
            }
        }
}

// ========== multi-output GEMM (QKV fused / A-Bm fused), bias optional ==========
struct MultiP {
    const __half* W[3];
    const float*  bias[3];
    float*        C32[3];
    __half*       C16[3];
};
__global__ void __launch_bounds__(256, 2)
gemm_multi(const __half* __restrict__ A, MultiP p, int nbnper, int K, int lda) {
    extern __shared__ __align__(16) __half sm[];
    __half* Asm = sm;
    __half* Bsm = sm + STAGES*A_ST;

    const int t = threadIdx.x, bm = blockIdx.y, bnG = blockIdx.x;
    const int sel = bnG / nbnper, bn = bnG % nbnper;
    const __half* W = p.W[sel];
    const float* bias = p.bias[sel];
    float* C32 = p.C32[sel];
    __half* C16 = p.C16[sel];

    const int lane = t & 31, wid = t >> 5;
    const int warpM = wid & 1, warpN = wid >> 1;
    const int g = lane >> 2, tg = lane & 3;
    const int ar = t >> 1, akc = (t & 1) * 8;
    const int bkr = t >> 4, bnc = (t & 15) * 8;
    const __half* Ab0 = A + (size_t)(bm*128) * lda;

    auto issueA = [&](int s, int k0) {
        cp16(smem_u32(Asm + s*A_ST + ar*24 + akc), Ab0 + (size_t)ar*lda + k0 + akc, true);
    };
    auto issueB = [&](int s, int k0) {
        cp16(smem_u32(Bsm + s*BNT_ST + bkr*136 + bnc),
             W + (size_t)(k0 + bkr)*D_ + bn*128 + bnc, true);
    };

    float acc[4][4][4];
#pragma unroll
    for (int i = 0; i < 4; i++)
#pragma unroll
        for (int j = 0; j < 4; j++)
#pragma unroll
            for (int c = 0; c < 4; c++) acc[i][j][c] = 0.f;

    const int l16 = lane & 15, lhi = lane >> 4;
    auto compute = [&](int s) {
        const __half* Ab = Asm + s*A_ST;
        const __half* Bb = Bsm + s*BNT_ST;
        uint32_t af[4][4], bf[4][2];
#pragma unroll
        for (int mt = 0; mt < 4; mt++)
            ldm_x4(af[mt], smem_u32(Ab + (warpM*64 + mt*16 + l16)*24 + lhi*8));
#pragma unroll
        for (int nt = 0; nt < 4; nt++)
            ldm_x2t(bf[nt], smem_u32(Bb + l16*136 + warpN*32 + nt*8));
#pragma unroll
        for (int mt = 0; mt < 4; mt++)
#pragma unroll
            for (int nt = 0; nt < 4; nt++) mma_h(acc[mt][nt], af[mt], bf[nt]);
    };

    const int nT = K >> 4;
#pragma unroll
    for (int s = 0; s < STAGES-1; s++) {
        if (s < nT) { issueA(s, s*16); issueB(s, s*16); }
        CP_COMMIT();
    }
    for (int ti = 0; ti < nT; ti++) {
        CP_WAIT(STAGES-2);
        __syncthreads();
        int nx = ti + STAGES - 1;
        if (nx < nT) { issueA(nx % STAGES, nx*16); issueB(nx % STAGES, nx*16); }
        CP_COMMIT();
        compute(ti % STAGES);
    }
#pragma unroll
    for (int mt = 0; mt < 4; mt++)
#pragma unroll
        for (int nt = 0; nt < 4; nt++) {
            int col = bn*128 + warpN*32 + nt*8 + 2*tg;
#pragma unroll
            for (int h = 0; h < 2; h++) {
                int row = bm*128 + warpM*64 + mt*16 + g + h*8;
                float v0 = acc[mt][nt][2*h], v1 = acc[mt][nt][2*h+1];
                if (bias) { v0 += bias[col]; v1 += bias[col+1]; }
                size_t o = (size_t)row*D_ + col;
                if (C32) *(float2*)(C32 + o) = make_float2(v0, v1);
                if (C16) *(__half2*)(C16 + o) = __floats2half2_rn(v0, v1);
            }
        }
}

// ====== relation GEMM: virtual rows gelu(Ar[i]+Br[j]) @ W2h + b (fp16 mma) ====
__global__ void __launch_bounds__(256, 2)
relgemm_h(const float* __restrict__ Ar, const float* __restrict__ Br,
          const __half* __restrict__ W, const float* __restrict__ bias,
          float* __restrict__ C) {
    extern __shared__ __align__(16) __half sm[];
    __half* Asm = sm;                    // [2][A_ST]
    __half* Bsm = sm + 2*A_ST;           // [STAGES][BNT_ST]

    const int t = threadIdx.x, bm = blockIdx.y, bn = blockIdx.x;
    const int lane = t & 31, wid = t >> 5;
    const int warpM = wid & 1, warpN = wid >> 1;
    const int g = lane >> 2, tg = lane & 3;
    const int r0 = t >> 2, akq = (t & 3) * 4;
    const int r1 = r0 + 64;
    const int bkr = t >> 4, bnc = (t & 15) * 8;

    const float *pa0, *pb0, *pa1, *pb1;
    {
        int m0 = bm*128 + r0, m1 = bm*128 + r1;
        int cb0 = (m0 >> 12) << 6, cb1 = (m1 >> 12) << 6;
        pa0 = Ar + (size_t)(cb0 + ((m0 >> 6) & 63)) * D_ + akq;
        pb0 = Br + (size_t)(cb0 + (m0 & 63)) * D_ + akq;
        pa1 = Ar + (size_t)(cb1 + ((m1 >> 6) & 63)) * D_ + akq;
        pb1 = Br + (size_t)(cb1 + (m1 & 63)) * D_ + akq;
    }

    float4 ua, va, ub, vb;
    auto loadA = [&](int k0) {
        ua = *(const float4*)(pa0 + k0); va = *(const float4*)(pb0 + k0);
        ub = *(const float4*)(pa1 + k0); vb = *(const float4*)(pb1 + k0);
    };
    auto storeA = [&](int s) {
        __half* dst = Asm + s*A_ST;
        __half2 x0 = __floats2half2_rn(gelu_f(ua.x+va.x), gelu_f(ua.y+va.y));
        __half2 x1 = __floats2half2_rn(gelu_f(ua.z+va.z), gelu_f(ua.w+va.w));
        *(uint2*)(dst + r0*24 + akq) = make_uint2(*(uint32_t*)&x0, *(uint32_t*)&x1);
        __half2 y0 = __floats2half2_rn(gelu_f(ub.x+vb.x), gelu_f(ub.y+vb.y));
        __half2 y1 = __floats2half2_rn(gelu_f(ub.z+vb.z), gelu_f(ub.w+vb.w));
        *(uint2*)(dst + r1*24 + akq) = make_uint2(*(uint32_t*)&y0, *(uint32_t*)&y1);
    };
    auto issueB = [&](int s, int k0) {
        cp16(smem_u32(Bsm + s*BNT_ST + bkr*136 + bnc),
             W + (size_t)(k0 + bkr)*D_ + bn*128 + bnc, true);
    };

    float acc[4][4][4];
#pragma unroll
    for (int i = 0; i < 4; i++)
#pragma unroll
        for (int j = 0; j < 4; j++)
#pragma unroll
            for (int c = 0; c < 4; c++) acc[i][j][c] = 0.f;

    const int l16 = lane & 15, lhi = lane >> 4;
    auto compute = [&](int sA, int sB) {
        const __half* Ab = Asm + sA*A_ST;
        const __half* Bb = Bsm + sB*BNT_ST;
        uint32_t af[4][4], bf[4][2];
#pragma unroll
        for (int mt = 0; mt < 4; mt++)
            ldm_x4(af[mt], smem_u32(Ab + (warpM*64 + mt*16 + l16)*24 + lhi*8));
#pragma unroll
        for (int nt = 0; nt < 4; nt++)
            ldm_x2t(bf[nt], smem_u32(Bb + l16*136 + warpN*32 + nt*8));
#pragma unroll
        for (int mt = 0; mt < 4; mt++)
#pragma unroll
            for (int nt = 0; nt < 4; nt++) mma_h(acc[mt][nt], af[mt], bf[nt]);
    };

    const int nT = D_ >> 4;   // 48
#pragma unroll
    for (int s = 0; s < STAGES-1; s++) { issueB(s, s*16); CP_COMMIT(); }
    loadA(0); storeA(0);
    for (int ti = 0; ti < nT; ti++) {
        if (ti + 1 < nT) loadA((ti+1)*16);
        CP_WAIT(STAGES-2);
        __syncthreads();
        int nx = ti + STAGES - 1;
        if (nx < nT) issueB(nx % STAGES, nx*16);
        CP_COMMIT();
        compute(ti & 1, ti % STAGES);
        if (ti + 1 < nT) storeA((ti+1) & 1);
    }
#pragma unroll
    for (int mt = 0; mt < 4; mt++)
#pragma unroll
        for (int nt = 0; nt < 4; nt++) {
            int row = bm*128 + warpM*64 + mt*16 + g;
            int col = bn*128 + warpN*32 + nt*8 + 2*tg;
            float b0 = bias[col], b1 = bias[col+1];
            *(float2*)(C + (size_t)row * D_ + col) =
                make_float2(acc[mt][nt][0] + b0, acc[mt][nt][1] + b1);
            *(float2*)(C + (size_t)(row + 8) * D_ + col) =
                make_float2(acc[mt][nt][2] + b0, acc[mt][nt][3] + b1);
        }
}

// ---------------- row LayerNorm (width 768) -> fp16 out ----------------
__launch_bounds__(256)
__global__ void ln_kernel(const float* __restrict__ x, const float* __restrict__ g,
                          const float* __restrict__ b, __half* __restrict__ out) {
    const int r = blockIdx.x, t = threadIdx.x;
    __shared__ float rs[8], rq[8], stat[2];
    const float* row = x + (size_t)r * D_;
    float v0 = row[t], v1 = row[t + 256], v2 = row[t + 512];
    float s = v0 + v1 + v2;
    float q = v0*v0 + v1*v1 + v2*v2;
#pragma unroll
    for (int o = 16; o > 0; o >>= 1) {
        s += __shfl_xor_sync(0xffffffffu, s, o);
        q += __shfl_xor_sync(0xffffffffu, q, o);
    }
    if ((t & 31) == 0) { rs[t >> 5] = s; rq[t >> 5] = q; }
    __syncthreads();
    if (t == 0) {
        float S = 0.f, Q = 0.f;
        for (int w = 0; w < 8; w++) { S += rs[w]; Q += rq[w]; }
        float mean = S * (1.f/768.f);
        float var  = Q * (1.f/768.f) - mean*mean;
        stat[0] = mean; stat[1] = rsqrtf(var + 1e-5f);
    }
    __syncthreads();
    float mean = stat[0], rstd = stat[1];
    __half* o = out + (size_t)r * D_;
    o[t]       = __float2half((v0 - mean) * rstd * g[t]       + b[t]);
    o[t + 256] = __float2half((v1 - mean) * rstd * g[t + 256] + b[t + 256]);
    o[t + 512] = __float2half((v2 - mean) * rstd * g[t + 512] + b[t + 512]);
}

// ------- softmax over rows of 1024: fp32 in, fp16 out -------
__launch_bounds__(256)
__global__ void softmax_k(const float* __restrict__ sc, __half* __restrict__ pr) {
    const int r = blockIdx.x, t = threadIdx.x;
    const float* row = sc + (size_t)r * 1024;
    __half* orow = pr + (size_t)r * 1024;
    __shared__ float red[8], stat[1];
    float v0 = row[t], v1 = row[t+256], v2 = row[t+512], v3 = row[t+768];
    float m = fmaxf(fmaxf(v0, v1), fmaxf(v2, v3));
#pragma unroll
    for (int o = 16; o > 0; o >>= 1) m = fmaxf(m, __shfl_xor_sync(0xffffffffu, m, o));
    if ((t & 31) == 0) red[t >> 5] = m;
    __syncthreads();
    if (t == 0) {
        float M = red[0];
        for (int w = 1; w < 8; w++) M = fmaxf(M, red[w]);
        stat[0] = M;
    }
    __syncthreads();
    float M = stat[0];
    v0 = expf(v0 - M); v1 = expf(v1 - M); v2 = expf(v2 - M); v3 = expf(v3 - M);
    float s = v0 + v1 + v2 + v3;
#pragma unroll
    for (int o = 16; o > 0; o >>= 1) s += __shfl_xor_sync(0xffffffffu, s, o);
    __syncthreads();
    if ((t & 31) == 0) red[t >> 5] = s;
    __syncthreads();
    if (t == 0) {
        float S = 0.f;
        for (int w = 0; w < 8; w++) S += red[w];
        stat[0] = 1.f / S;
    }
    __syncthreads();
    float inv = stat[0];
    orow[t]     = __float2half(v0*inv);
    orow[t+256] = __float2half(v1*inv);
    orow[t+512] = __float2half(v2*inv);
    orow[t+768] = __float2half(v3*inv);
}

// ---- relreduce: warp-per-j-row LN + mean over j + residual + fused LN2 ----
__launch_bounds__(256)
__global__ void relreduce(const float* __restrict__ Hp, const float* __restrict__ g,
                          const float* __restrict__ bln, const float* __restrict__ x1,
                          float* __restrict__ x2,
                          const float* __restrict__ ln2g, const float* __restrict__ ln2b,
                          __half* __restrict__ hout) {
    const int bci = blockIdx.x, t = threadIdx.x;
    const int w = t >> 5, lane = t & 31;
    __shared__ float smacc[8][768];
    __shared__ float rs[8], rq[8], stat[2];

    float acc[24];
#pragma unroll
    for (int e = 0; e < 24; e++) acc[e] = 0.f;

    const float* base = Hp + (size_t)bci * 64 * D_;
    for (int jj = 0; jj < 8; jj++) {
        const float* row = base + (size_t)(w + jj*8) * D_;
        float v[24]; float s = 0.f, q = 0.f;
#pragma unroll
        for (int e = 0; e < 24; e++) {
            v[e] = row[lane + 32*e];
            s += v[e]; q += v[e]*v[e];
        }
#pragma unroll
        for (int o = 16; o > 0; o >>= 1) {
            s += __shfl_xor_sync(0xffffffffu, s, o);
            q += __shfl_xor_sync(0xffffffffu, q, o);
        }
        float mean = s * (1.f/768.f);
        float rstd = rsqrtf(q * (1.f/768.f) - mean*mean + 1e-5f);
#pragma unroll
        for (int e = 0; e < 24; e++) acc[e] += (v[e] - mean) * rstd;
    }
#pragma unroll
    for (int e = 0; e < 24; e++) smacc[w][lane + 32*e] = acc[e];
    __syncthreads();

    float o0 = 0.f, o1 = 0.f, o2 = 0.f;
#pragma unroll
    for (int w8 = 0; w8 < 8; w8++) {
        o0 += smacc[w8][t];
        o1 += smacc[w8][t + 256];
        o2 += smacc[w8][t + 512];
    }
    size_t off = (size_t)bci * D_;
    o0 = x1[off + t]       + o0 * (1.f/64.f) * g[t]       + bln[t];
    o1 = x1[off + t + 256] + o1 * (1.f/64.f) * g[t + 256] + bln[t + 256];
    o2 = x1[off + t + 512] + o2 * (1.f/64.f) * g[t + 512] + bln[t + 512];
    x2[off + t] = o0; x2[off + t + 256] = o1; x2[off + t + 512] = o2;

    float s = o0 + o1 + o2, q = o0*o0 + o1*o1 + o2*o2;
#pragma unroll
    for (int o = 16; o > 0; o >>= 1) {
        s += __shfl_xor_sync(0xffffffffu, s, o);
        q += __shfl_xor_sync(0xffffffffu, q, o);
    }
    if (lane == 0) { rs[w] = s; rq[w] = q; }
    __syncthreads();
    if (t == 0) {
        float S = 0.f, Q = 0.f;
        for (int w8 = 0; w8 < 8; w8++) { S += rs[w8]; Q += rq[w8]; }
        float mean = S * (1.f/768.f);
        float var  = Q * (1.f/768.f) - mean*mean;
        stat[0] = mean; stat[1] = rsqrtf(var + 1e-5f);
    }
    __syncthreads();
    float mean = stat[0], rstd = stat[1];
    hout[off + t]       = __float2half((o0 - mean) * rstd * ln2g[t]       + ln2b[t]);
    hout[off + t + 256] = __float2half((o1 - mean) * rstd * ln2g[t + 256] + ln2b[t + 256]);
    hout[off + t + 512] = __float2half((o2 - mean) * rstd * ln2g[t + 512] + ln2b[t + 512]);
}

// ---------------- host orchestration ----------------
static float  *P_x1, *P_A, *P_Bm, *P_x2, *P_Hp;
static __half *P_hh, *P_qh, *P_kh, *P_vh, *P_ctxh, *P_x1h, *P_fh, *P_ph;
static __half *P_Wqh, *P_Wkh, *P_Wvh, *P_Woh, *P_W1h, *P_W2h, *P_E1h, *P_E2h;
static bool g_init = false;

#define SM_NT  ((STAGES*A_ST + STAGES*BNT_ST)*2)   // (12288+8704)*2 = 41984
#define SM_T   ((STAGES*A_ST + STAGES*BT_ST)*2)    // 49152
#define SM_REL ((2*A_ST + STAGES*BNT_ST)*2)        // 29696

extern "C" void kernel_launch(void* const* d_in, const int* in_sizes, int n_in,
                              void* d_out, int out_size) {
    if (!g_init) {
        cudaGetSymbolAddress((void**)&P_x1,  g_x1);
        cudaGetSymbolAddress((void**)&P_A,   g_A);
        cudaGetSymbolAddress((void**)&P_Bm,  g_Bm);
        cudaGetSymbolAddress((void**)&P_x2,  g_x2);
        cudaGetSymbolAddress((void**)&P_Hp,  g_Hp);
        cudaGetSymbolAddress((void**)&P_hh,  g_hh);
        cudaGetSymbolAddress((void**)&P_qh,  g_qh);
        cudaGetSymbolAddress((void**)&P_kh,  g_kh);
        cudaGetSymbolAddress((void**)&P_vh,  g_vh);
        cudaGetSymbolAddress((void**)&P_ctxh,g_ctxh);
        cudaGetSymbolAddress((void**)&P_x1h, g_x1h);
        cudaGetSymbolAddress((void**)&P_fh,  g_fh);
        cudaGetSymbolAddress((void**)&P_ph,  g_ph);
        cudaGetSymbolAddress((void**)&P_Wqh, g_Wqh);
        cudaGetSymbolAddress((void**)&P_Wkh, g_Wkh);
        cudaGetSymbolAddress((void**)&P_Wvh, g_Wvh);
        cudaGetSymbolAddress((void**)&P_Woh, g_Woh);
        cudaGetSymbolAddress((void**)&P_W1h, g_W1h);
        cudaGetSymbolAddress((void**)&P_W2h, g_W2h);
        cudaGetSymbolAddress((void**)&P_E1h, g_E1h);
        cudaGetSymbolAddress((void**)&P_E2h, g_E2h);
        cudaFuncSetAttribute(gemm_h<4,true,true,false>,  cudaFuncAttributeMaxDynamicSharedMemorySize, SM_T);
        cudaFuncSetAttribute(gemm_h<0,false,false,true>, cudaFuncAttributeMaxDynamicSharedMemorySize, SM_NT);
        cudaFuncSetAttribute(gemm_h<3,false,true,true>,  cudaFuncAttributeMaxDynamicSharedMemorySize, SM_NT);
        cudaFuncSetAttribute(gemm_h<2,false,false,true>, cudaFuncAttributeMaxDynamicSharedMemorySize, SM_NT);
        cudaFuncSetAttribute(gemm_h<3,false,true,false>, cudaFuncAttributeMaxDynamicSharedMemorySize, SM_NT);
        cudaFuncSetAttribute(gemm_multi, cudaFuncAttributeMaxDynamicSharedMemorySize, SM_NT);
        cudaFuncSetAttribute(relgemm_h,  cudaFuncAttributeMaxDynamicSharedMemorySize, SM_REL);
        g_init = true;
    }
    const float* x      = (const float*)d_in[0];
    const float* Wq     = (const float*)d_in[1];
    const float* bq     = (const float*)d_in[2];
    const float* Wk     = (const float*)d_in[3];
    const float* bk     = (const float*)d_in[4];
    const float* Wv     = (const float*)d_in[5];
    const float* bv     = (const float*)d_in[6];
    const float* Wo     = (const float*)d_in[7];
    const float* bo     = (const float*)d_in[8];
    const float* ln1_g  = (const float*)d_in[9];
    const float* ln1_b  = (const float*)d_in[10];
    const float* rel_W1 = (const float*)d_in[11];
    const float* rel_b1 = (const float*)d_in[12];
    const float* rel_W2 = (const float*)d_in[13];
    const float* rel_b2 = (const float*)d_in[14];
    const float* rel_ln_g = (const float*)d_in[15];
    const float* rel_ln_b = (const float*)d_in[16];
    const float* ln2_g  = (const float*)d_in[17];
    const float* ln2_b  = (const float*)d_in[18];
    const float* enc_W1 = (const float*)d_in[19];
    const float* enc_b1 = (const float*)d_in[20];
    const float* enc_W2 = (const float*)d_in[21];
    const float* enc_b2 = (const float*)d_in[22];
    float* out = (float*)d_out;

    const long long SD = (long long)S_ * D_;
    const long long SS = (long long)S_ * S_;
    const int DD = D_ * D_;

    // 0) weight conversions
    conv_h<<<DD/1024, 256>>>(Wq, P_Wqh, DD);
    conv_h<<<DD/1024, 256>>>(Wk, P_Wkh, DD);
    conv_h<<<DD/1024, 256>>>(Wv, P_Wvh, DD);
    conv_h<<<DD/1024, 256>>>(Wo, P_Woh, DD);
    conv_h<<<2*DD/1024, 256>>>(rel_W1, P_W1h, 2*DD);
    conv_h<<<DD/1024, 256>>>(rel_W2, P_W2h, DD);
    conv_h<<<D_*DFF_/1024, 256>>>(enc_W1, P_E1h, D_*DFF_);
    conv_h<<<D_*DFF_/1024, 256>>>(enc_W2, P_E2h, D_*DFF_);

    // 1) h = LN1(x) -> fp16
    ln_kernel<<<BS_, 256>>>(x, ln1_g, ln1_b, P_hh);
    // 2) fused QKV
    {
        MultiP p;
        p.W[0]=P_Wqh; p.W[1]=P_Wkh; p.W[2]=P_Wvh;
        p.bias[0]=bq; p.bias[1]=bk; p.bias[2]=bv;
        p.C32[0]=p.C32[1]=p.C32[2]=nullptr;
        p.C16[0]=P_qh; p.C16[1]=P_kh; p.C16[2]=P_vh;
        gemm_multi<<<dim3(18,16), 256, SM_NT>>>(P_hh, p, 6, D_, D_);
    }
    // 3) attention
    gemm_h<4,true,true,false><<<dim3(8,8,B_*H_), 256, SM_T>>>(
        P_qh, P_kh, nullptr, nullptr, P_Hp, nullptr,
        S_, S_, 64, D_, D_, S_, SD, 64, SD, 64, (long long)H_*SS, SS);
    softmax_k<<<B_*H_*S_, 256>>>(P_Hp, P_ph);
    gemm_h<0,false,false,true><<<dim3(1,8,B_*H_), 256, SM_NT>>>(
        P_ph, P_vh, nullptr, nullptr, nullptr, P_ctxh,
        S_, 64, S_, S_, D_, D_, (long long)H_*SS, SS, SD, 64, SD, 64);
    // 4) x1 = x + ctx@Wo + bo  (fp32 + fp16 copies)
    gemm_h<3,false,true,true><<<dim3(6,16), 256, SM_NT>>>(
        P_ctxh, P_Woh, bo, x, P_x1, P_x1h,
        BS_, D_, D_, D_, D_, D_, 0,0,0,0,0,0);
    // 5) fused A / Bm
    {
        MultiP p;
        p.W[0]=P_W1h; p.W[1]=P_W1h + DD; p.W[2]=nullptr;
        p.bias[0]=rel_b1; p.bias[1]=nullptr; p.bias[2]=nullptr;
        p.C32[0]=P_A; p.C32[1]=P_Bm; p.C32[2]=nullptr;
        p.C16[0]=p.C16[1]=p.C16[2]=nullptr;
        gemm_multi<<<dim3(12,16), 256, SM_NT>>>(P_x1h, p, 6, D_, D_);
    }
    // 6) relation pairwise GEMM + fused reduction (+LN2)
    relgemm_h<<<dim3(6, MREL/128), 256, SM_REL>>>(P_A, P_Bm, P_W2h, rel_b2, P_Hp);
    relreduce<<<BS_, 256>>>(P_Hp, rel_ln_g, rel_ln_b, P_x1, P_x2, ln2_g, ln2_b, P_hh);
    // 7) FFN
    gemm_h<2,false,false,true><<<dim3(24,16), 256, SM_NT>>>(
        P_hh, P_E1h, enc_b1, nullptr, nullptr, P_fh,
        BS_, DFF_, D_, D_, DFF_, DFF_, 0,0,0,0,0,0);
    gemm_h<3,false,true,false><<<dim3(6,16), 256, SM_NT>>>(
        P_fh, P_E2h, enc_b2, P_x2, out, nullptr,
        BS_, D_, DFF_, DFF_, D_, D_, 0,0,0,0,0,0);
}

// round 5
// speedup vs baseline: 5.3614x; 1.4541x over previous
#include <cuda_runtime.h>
#include <cuda_fp16.h>
#include <math.h>
#include <stdint.h>

#define B_   2
#define S_   1024
#define D_   768
#define H_   12
#define DFF_ 3072
#define BS_  2048
#define MREL 131072
#define STAGES 4

// ---------------- scratch ----------------
__device__ float  g_x1 [BS_*D_];
__device__ float  g_A  [BS_*D_];
__device__ float  g_Bm [BS_*D_];
__device__ float  g_x2 [BS_*D_];
__device__ float  g_sc [(size_t)B_*H_*S_*S_];   // attn scores fp32 (100MB)
__device__ __half g_Hp [(size_t)MREL*D_];       // relation out fp16 (201MB)
__device__ __half g_G  [(size_t)MREL*D_];       // gelu(A_i+B_j) fp16 (201MB)
__device__ __half g_hh [BS_*D_];
__device__ __half g_qh [BS_*D_];
__device__ __half g_kh [BS_*D_];
__device__ __half g_vh [BS_*D_];
__device__ __half g_ctxh[BS_*D_];
__device__ __half g_x1h[BS_*D_];
__device__ __half g_fh [BS_*DFF_];
__device__ __half g_ph [(size_t)B_*H_*S_*S_];   // softmax probs fp16 (50MB)
// fp16 weights
__device__ __half g_Wqh[D_*D_], g_Wkh[D_*D_], g_Wvh[D_*D_], g_Woh[D_*D_];
__device__ __half g_W1h[2*D_*D_], g_W2h[D_*D_];
__device__ __half g_E1h[D_*DFF_], g_E2h[DFF_*D_];

__device__ __forceinline__ float gelu_f(float x) {
    return 0.5f * x * (1.0f + erff(x * 0.70710678118654752f));
}
__device__ __forceinline__ uint32_t smem_u32(const void* p) {
    return (uint32_t)__cvta_generic_to_shared(p);
}
__device__ __forceinline__ void cp16(uint32_t dst, const void* src, bool pred) {
    int sz = pred ? 16 : 0;
    asm volatile("cp.async.cg.shared.global [%0], [%1], 16, %2;\n"
                 :: "r"(dst), "l"(src), "r"(sz));
}
#define CP_COMMIT() asm volatile("cp.async.commit_group;\n")
#define CP_WAIT(n)  asm volatile("cp.async.wait_group %0;\n" :: "n"(n))

__device__ __forceinline__ void ldm_x4(uint32_t* r, uint32_t a) {
    asm volatile("ldmatrix.sync.aligned.m8n8.x4.shared.b16 {%0,%1,%2,%3},[%4];"
                 : "=r"(r[0]), "=r"(r[1]), "=r"(r[2]), "=r"(r[3]) : "r"(a));
}
__device__ __forceinline__ void ldm_x2t(uint32_t* r, uint32_t a) {
    asm volatile("ldmatrix.sync.aligned.m8n8.x2.trans.shared.b16 {%0,%1},[%2];"
                 : "=r"(r[0]), "=r"(r[1]) : "r"(a));
}
__device__ __forceinline__ void ldm_x2(uint32_t* r, uint32_t a) {
    asm volatile("ldmatrix.sync.aligned.m8n8.x2.shared.b16 {%0,%1},[%2];"
                 : "=r"(r[0]), "=r"(r[1]) : "r"(a));
}
__device__ __forceinline__ void mma_h(float* c, const uint32_t* a, const uint32_t* b) {
    asm volatile(
        "mma.sync.aligned.m16n8k16.row.col.f32.f16.f16.f32 "
        "{%0,%1,%2,%3},{%4,%5,%6,%7},{%8,%9},{%0,%1,%2,%3};\n"
        : "+f"(c[0]), "+f"(c[1]), "+f"(c[2]), "+f"(c[3])
        : "r"(a[0]), "r"(a[1]), "r"(a[2]), "r"(a[3]), "r"(b[0]), "r"(b[1]));
}

// ---------------- fused fp32 -> fp16 conversion over 8 segments ----------------
struct ConvP {
    const float* src[8];
    __half* dst[8];
    int off[9];     // cumulative element offsets, off[8] = total
};
__global__ void conv_all(ConvP p) {
    int e = (blockIdx.x * 256 + threadIdx.x) * 4;
    if (e >= p.off[8]) return;
    int s = 0;
#pragma unroll
    for (int k = 0; k < 7; k++) s += (e >= p.off[k+1]);
    int le = e - p.off[s];
    float4 v = *(const float4*)(p.src[s] + le);
    __half2 a = __floats2half2_rn(v.x, v.y);
    __half2 b = __floats2half2_rn(v.z, v.w);
    *(uint2*)(p.dst[s] + le) = make_uint2(*(uint32_t*)&a, *(uint32_t*)&b);
}

// ---------------- G = gelu(A_i + B_j) materialization (fp16) ----------------
// block: (bc*64+i) from blockIdx.x (0..2047), j-half from blockIdx.y, 192 threads
__global__ void __launch_bounds__(192)
gelu_mat(const float* __restrict__ A, const float* __restrict__ Bm,
         __half* __restrict__ G) {
    const int bx = blockIdx.x, jh = blockIdx.y, t = threadIdx.x;
    const int cb = (bx >> 6) << 6;       // bc*64
    const int i  = bx & 63;
    float4 a = *(const float4*)(A + (size_t)(cb + i) * D_ + t*4);
    const float* Bbase = Bm + (size_t)cb * D_ + t*4;
    __half* Gb = G + (size_t)bx * 64 * D_ + t*4;
#pragma unroll 4
    for (int j = jh*32; j < jh*32 + 32; j++) {
        float4 b = *(const float4*)(Bbase + (size_t)j * D_);
        __half2 h0 = __floats2half2_rn(gelu_f(a.x+b.x), gelu_f(a.y+b.y));
        __half2 h1 = __floats2half2_rn(gelu_f(a.z+b.z), gelu_f(a.w+b.w));
        *(uint2*)(Gb + (size_t)j * D_) = make_uint2(*(uint32_t*)&h0, *(uint32_t*)&h1);
    }
}

// smem geometry (halves)
#define A_ST   (128*24)
#define BNT_ST (16*136)
#define BT_ST  (128*24)

// ========== generic fp16 GEMM, BM=BN=128, BK=16, 4-stage cp.async ==========
// EPI: 0=none 1=bias 2=bias+gelu 3=bias+res 4=*0.125
template<int EPI, bool BTRANS, bool O32, bool O16>
__global__ void __launch_bounds__(256, 2)
gemm_h(const __half* __restrict__ A, const __half* __restrict__ Bm_,
       const float* __restrict__ bias, const float* __restrict__ res,
       float* __restrict__ C32, __half* __restrict__ C16,
       int M, int N, int K, int lda, int ldb, int ldc,
       long long aSB, long long aSH, long long bSB, long long bSH,
       long long cSB, long long cSH) {
    extern __shared__ __align__(16) __half sm[];
    constexpr int BSZ = BTRANS ? BT_ST : BNT_ST;
    __half* Asm = sm;
    __half* Bsm = sm + STAGES*A_ST;

    const int t = threadIdx.x, bm = blockIdx.y, bn = blockIdx.x, z = blockIdx.z;
    A   += (z / H_) * aSB + (z % H_) * aSH;
    Bm_ += (z / H_) * bSB + (z % H_) * bSH;
    long long cOff = (z / H_) * cSB + (z % H_) * cSH;
    const int lane = t & 31, wid = t >> 5;
    const int warpM = wid & 1, warpN = wid >> 1;
    const int g = lane >> 2, tg = lane & 3;

    const int ar = t >> 1, akc = (t & 1) * 8;
    const int bkr = t >> 4, bnc = (t & 15) * 8;

    const __half* Ab0 = A + (size_t)(bm*128) * lda;

    auto issueA = [&](int s, int k0) {
        __half* dst = Asm + s*A_ST;
        cp16(smem_u32(dst + ar*24 + akc), Ab0 + (size_t)ar*lda + k0 + akc, true);
    };
    auto issueB = [&](int s, int k0) {
        __half* dst = Bsm + s*BSZ;
        if (!BTRANS) {
            bool p = (bn*128 + bnc) < N;
            cp16(smem_u32(dst + bkr*136 + bnc),
                 Bm_ + (size_t)(k0 + bkr)*ldb + bn*128 + bnc, p);
        } else {
            bool p = (bn*128 + ar) < N;
            cp16(smem_u32(dst + ar*24 + akc),
                 Bm_ + (size_t)(bn*128 + ar)*ldb + k0 + akc, p);
        }
    };

    float acc[4][4][4];
#pragma unroll
    for (int i = 0; i < 4; i++)
#pragma unroll
        for (int j = 0; j < 4; j++)
#pragma unroll
            for (int c = 0; c < 4; c++) acc[i][j][c] = 0.f;

    const int l16 = lane & 15, lhi = lane >> 4;
    auto compute = [&](int s) {
        const __half* Ab = Asm + s*A_ST;
        const __half* Bb = Bsm + s*BSZ;
        uint32_t af[4][4], bf[4][2];
#pragma unroll
        for (int mt = 0; mt < 4; mt++) {
            int m0 = warpM*64 + mt*16;
            ldm_x4(af[mt], smem_u32(Ab + (m0 + l16)*24 + lhi*8));
        }
#pragma unroll
        for (int nt = 0; nt < 4; nt++) {
            int n0 = warpN*32 + nt*8;
            if (!BTRANS) ldm_x2t(bf[nt], smem_u32(Bb + l16*136 + n0));
            else         ldm_x2 (bf[nt], smem_u32(Bb + (n0 + (l16 & 7))*24 + (l16 >> 3)*8));
        }
#pragma unroll
        for (int mt = 0; mt < 4; mt++)
#pragma unroll
            for (int nt = 0; nt < 4; nt++) mma_h(acc[mt][nt], af[mt], bf[nt]);
    };

    const int nT = K >> 4;
#pragma unroll
    for (int s = 0; s < STAGES-1; s++) {
        if (s < nT) { issueA(s, s*16); issueB(s, s*16); }
        CP_COMMIT();
    }
    for (int ti = 0; ti < nT; ti++) {
        CP_WAIT(STAGES-2);
        __syncthreads();
        int nx = ti + STAGES - 1;
        if (nx < nT) { issueA(nx % STAGES, nx*16); issueB(nx % STAGES, nx*16); }
        CP_COMMIT();
        compute(ti % STAGES);
    }
#pragma unroll
    for (int mt = 0; mt < 4; mt++)
#pragma unroll
        for (int nt = 0; nt < 4; nt++) {
            int col = bn*128 + warpN*32 + nt*8 + 2*tg;
            if (col >= N) continue;
#pragma unroll
            for (int h = 0; h < 2; h++) {
                int row = bm*128 + warpM*64 + mt*16 + g + h*8;
                float v0 = acc[mt][nt][2*h], v1 = acc[mt][nt][2*h+1];
                if (EPI == 1 || EPI == 2 || EPI == 3) { v0 += bias[col]; v1 += bias[col+1]; }
                if (EPI == 2) { v0 = gelu_f(v0); v1 = gelu_f(v1); }
                if (EPI == 3) { size_t o = (size_t)row*ldc + col; v0 += res[o]; v1 += res[o+1]; }
                if (EPI == 4) { v0 *= 0.125f; v1 *= 0.125f; }
                size_t o = cOff + (size_t)row*ldc + col;
                if (O32) *(float2*)(C32 + o) = make_float2(v0, v1);
                if (O16) *(__half2*)(C16 + o) = __floats2half2_rn(v0, v1);
            }
        }
}

// ========== multi-output GEMM (QKV fused / A-Bm fused) ==========
struct MultiP {
    const __half* W[3];
    const float*  bias[3];
    float*        C32[3];
    __half*       C16[3];
};
__global__ void __launch_bounds__(256, 2)
gemm_multi(const __half* __restrict__ A, MultiP p, int nbnper, int K, int lda) {
    extern __shared__ __align__(16) __half sm[];
    __half* Asm = sm;
    __half* Bsm = sm + STAGES*A_ST;

    const int t = threadIdx.x, bm = blockIdx.y, bnG = blockIdx.x;
    const int sel = bnG / nbnper, bn = bnG % nbnper;
    const __half* W = p.W[sel];
    const float* bias = p.bias[sel];
    float* C32 = p.C32[sel];
    __half* C16 = p.C16[sel];

    const int lane = t & 31, wid = t >> 5;
    const int warpM = wid & 1, warpN = wid >> 1;
    const int g = lane >> 2, tg = lane & 3;
    const int ar = t >> 1, akc = (t & 1) * 8;
    const int bkr = t >> 4, bnc = (t & 15) * 8;
    const __half* Ab0 = A + (size_t)(bm*128) * lda;

    auto issueA = [&](int s, int k0) {
        cp16(smem_u32(Asm + s*A_ST + ar*24 + akc), Ab0 + (size_t)ar*lda + k0 + akc, true);
    };
    auto issueB = [&](int s, int k0) {
        cp16(smem_u32(Bsm + s*BNT_ST + bkr*136 + bnc),
             W + (size_t)(k0 + bkr)*D_ + bn*128 + bnc, true);
    };

    float acc[4][4][4];
#pragma unroll
    for (int i = 0; i < 4; i++)
#pragma unroll
        for (int j = 0; j < 4; j++)
#pragma unroll
            for (int c = 0; c < 4; c++) acc[i][j][c] = 0.f;

    const int l16 = lane & 15, lhi = lane >> 4;
    auto compute = [&](int s) {
        const __half* Ab = Asm + s*A_ST;
        const __half* Bb = Bsm + s*BNT_ST;
        uint32_t af[4][4], bf[4][2];
#pragma unroll
        for (int mt = 0; mt < 4; mt++)
            ldm_x4(af[mt], smem_u32(Ab + (warpM*64 + mt*16 + l16)*24 + lhi*8));
#pragma unroll
        for (int nt = 0; nt < 4; nt++)
            ldm_x2t(bf[nt], smem_u32(Bb + l16*136 + warpN*32 + nt*8));
#pragma unroll
        for (int mt = 0; mt < 4; mt++)
#pragma unroll
            for (int nt = 0; nt < 4; nt++) mma_h(acc[mt][nt], af[mt], bf[nt]);
    };

    const int nT = K >> 4;
#pragma unroll
    for (int s = 0; s < STAGES-1; s++) {
        if (s < nT) { issueA(s, s*16); issueB(s, s*16); }
        CP_COMMIT();
    }
    for (int ti = 0; ti < nT; ti++) {
        CP_WAIT(STAGES-2);
        __syncthreads();
        int nx = ti + STAGES - 1;
        if (nx < nT) { issueA(nx % STAGES, nx*16); issueB(nx % STAGES, nx*16); }
        CP_COMMIT();
        compute(ti % STAGES);
    }
#pragma unroll
    for (int mt = 0; mt < 4; mt++)
#pragma unroll
        for (int nt = 0; nt < 4; nt++) {
            int col = bn*128 + warpN*32 + nt*8 + 2*tg;
#pragma unroll
            for (int h = 0; h < 2; h++) {
                int row = bm*128 + warpM*64 + mt*16 + g + h*8;
                float v0 = acc[mt][nt][2*h], v1 = acc[mt][nt][2*h+1];
                if (bias) { v0 += bias[col]; v1 += bias[col+1]; }
                size_t o = (size_t)row*D_ + col;
                if (C32) *(float2*)(C32 + o) = make_float2(v0, v1);
                if (C16) *(__half2*)(C16 + o) = __floats2half2_rn(v0, v1);
            }
        }
}

// ---------------- row LayerNorm (width 768) -> fp16 out ----------------
__launch_bounds__(256)
__global__ void ln_kernel(const float* __restrict__ x, const float* __restrict__ g,
                          const float* __restrict__ b, __half* __restrict__ out) {
    const int r = blockIdx.x, t = threadIdx.x;
    __shared__ float rs[8], rq[8], stat[2];
    const float* row = x + (size_t)r * D_;
    float v0 = row[t], v1 = row[t + 256], v2 = row[t + 512];
    float s = v0 + v1 + v2;
    float q = v0*v0 + v1*v1 + v2*v2;
#pragma unroll
    for (int o = 16; o > 0; o >>= 1) {
        s += __shfl_xor_sync(0xffffffffu, s, o);
        q += __shfl_xor_sync(0xffffffffu, q, o);
    }
    if ((t & 31) == 0) { rs[t >> 5] = s; rq[t >> 5] = q; }
    __syncthreads();
    if (t == 0) {
        float S = 0.f, Q = 0.f;
        for (int w = 0; w < 8; w++) { S += rs[w]; Q += rq[w]; }
        float mean = S * (1.f/768.f);
        float var  = Q * (1.f/768.f) - mean*mean;
        stat[0] = mean; stat[1] = rsqrtf(var + 1e-5f);
    }
    __syncthreads();
    float mean = stat[0], rstd = stat[1];
    __half* o = out + (size_t)r * D_;
    o[t]       = __float2half((v0 - mean) * rstd * g[t]       + b[t]);
    o[t + 256] = __float2half((v1 - mean) * rstd * g[t + 256] + b[t + 256]);
    o[t + 512] = __float2half((v2 - mean) * rstd * g[t + 512] + b[t + 512]);
}

// ------- softmax over rows of 1024: fp32 in, fp16 out -------
__launch_bounds__(256)
__global__ void softmax_k(const float* __restrict__ sc, __half* __restrict__ pr) {
    const int r = blockIdx.x, t = threadIdx.x;
    const float* row = sc + (size_t)r * 1024;
    __half* orow = pr + (size_t)r * 1024;
    __shared__ float red[8], stat[1];
    float v0 = row[t], v1 = row[t+256], v2 = row[t+512], v3 = row[t+768];
    float m = fmaxf(fmaxf(v0, v1), fmaxf(v2, v3));
#pragma unroll
    for (int o = 16; o > 0; o >>= 1) m = fmaxf(m, __shfl_xor_sync(0xffffffffu, m, o));
    if ((t & 31) == 0) red[t >> 5] = m;
    __syncthreads();
    if (t == 0) {
        float M = red[0];
        for (int w = 1; w < 8; w++) M = fmaxf(M, red[w]);
        stat[0] = M;
    }
    __syncthreads();
    float M = stat[0];
    v0 = expf(v0 - M); v1 = expf(v1 - M); v2 = expf(v2 - M); v3 = expf(v3 - M);
    float s = v0 + v1 + v2 + v3;
#pragma unroll
    for (int o = 16; o > 0; o >>= 1) s += __shfl_xor_sync(0xffffffffu, s, o);
    __syncthreads();
    if ((t & 31) == 0) red[t >> 5] = s;
    __syncthreads();
    if (t == 0) {
        float S = 0.f;
        for (int w = 0; w < 8; w++) S += red[w];
        stat[0] = 1.f / S;
    }
    __syncthreads();
    float inv = stat[0];
    orow[t]     = __float2half(v0*inv);
    orow[t+256] = __float2half(v1*inv);
    orow[t+512] = __float2half(v2*inv);
    orow[t+768] = __float2half(v3*inv);
}

// ---- relreduce: warp-per-j-row LN + mean over j + residual + fused LN2 ----
// Hp rows fp16; warp loads half2 pairs.
__launch_bounds__(256)
__global__ void relreduce(const __half* __restrict__ Hp, const float* __restrict__ g,
                          const float* __restrict__ bln, const float* __restrict__ x1,
                          float* __restrict__ x2,
                          const float* __restrict__ ln2g, const float* __restrict__ ln2b,
                          __half* __restrict__ hout) {
    const int bci = blockIdx.x, t = threadIdx.x;
    const int w = t >> 5, lane = t & 31;
    __shared__ float smacc[8][768];
    __shared__ float rs[8], rq[8], stat[2];

    float acc[24];
#pragma unroll
    for (int e = 0; e < 24; e++) acc[e] = 0.f;

    const __half* base = Hp + (size_t)bci * 64 * D_;
    for (int jj = 0; jj < 8; jj++) {
        const __half2* row = (const __half2*)(base + (size_t)(w + jj*8) * D_);
        float v[24]; float s = 0.f, q = 0.f;
#pragma unroll
        for (int e = 0; e < 12; e++) {
            float2 f = __half22float2(row[lane + 32*e]);
            v[2*e] = f.x; v[2*e+1] = f.y;
            s += f.x + f.y; q += f.x*f.x + f.y*f.y;
        }
#pragma unroll
        for (int o = 16; o > 0; o >>= 1) {
            s += __shfl_xor_sync(0xffffffffu, s, o);
            q += __shfl_xor_sync(0xffffffffu, q, o);
        }
        float mean = s * (1.f/768.f);
        float rstd = rsqrtf(q * (1.f/768.f) - mean*mean + 1e-5f);
#pragma unroll
        for (int e = 0; e < 24; e++) acc[e] += (v[e] - mean) * rstd;
    }
#pragma unroll
    for (int e = 0; e < 12; e++) {
        smacc[w][2*(lane + 32*e)]     = acc[2*e];
        smacc[w][2*(lane + 32*e) + 1] = acc[2*e+1];
    }
    __syncthreads();

    float o0 = 0.f, o1 = 0.f, o2 = 0.f;
#pragma unroll
    for (int w8 = 0; w8 < 8; w8++) {
        o0 += smacc[w8][t];
        o1 += smacc[w8][t + 256];
        o2 += smacc[w8][t + 512];
    }
    size_t off = (size_t)bci * D_;
    o0 = x1[off + t]       + o0 * (1.f/64.f) * g[t]       + bln[t];
    o1 = x1[off + t + 256] + o1 * (1.f/64.f) * g[t + 256] + bln[t + 256];
    o2 = x1[off + t + 512] + o2 * (1.f/64.f) * g[t + 512] + bln[t + 512];
    x2[off + t] = o0; x2[off + t + 256] = o1; x2[off + t + 512] = o2;

    float s = o0 + o1 + o2, q = o0*o0 + o1*o1 + o2*o2;
#pragma unroll
    for (int o = 16; o > 0; o >>= 1) {
        s += __shfl_xor_sync(0xffffffffu, s, o);
        q += __shfl_xor_sync(0xffffffffu, q, o);
    }
    if (lane == 0) { rs[w] = s; rq[w] = q; }
    __syncthreads();
    if (t == 0) {
        float S = 0.f, Q = 0.f;
        for (int w8 = 0; w8 < 8; w8++) { S += rs[w8]; Q += rq[w8]; }
        float mean = S * (1.f/768.f);
        float var  = Q * (1.f/768.f) - mean*mean;
        stat[0] = mean; stat[1] = rsqrtf(var + 1e-5f);
    }
    __syncthreads();
    float mean = stat[0], rstd = stat[1];
    hout[off + t]       = __float2half((o0 - mean) * rstd * ln2g[t]       + ln2b[t]);
    hout[off + t + 256] = __float2half((o1 - mean) * rstd * ln2g[t + 256] + ln2b[t + 256]);
    hout[off + t + 512] = __float2half((o2 - mean) * rstd * ln2g[t + 512] + ln2b[t + 512]);
}

// ---------------- host orchestration ----------------
static float  *P_x1, *P_A, *P_Bm, *P_x2, *P_sc;
static __half *P_Hp, *P_G;
static __half *P_hh, *P_qh, *P_kh, *P_vh, *P_ctxh, *P_x1h, *P_fh, *P_ph;
static __half *P_Wqh, *P_Wkh, *P_Wvh, *P_Woh, *P_W1h, *P_W2h, *P_E1h, *P_E2h;
static bool g_init = false;

#define SM_NT  ((STAGES*A_ST + STAGES*BNT_ST)*2)
#define SM_T   ((STAGES*A_ST + STAGES*BT_ST)*2)

extern "C" void kernel_launch(void* const* d_in, const int* in_sizes, int n_in,
                              void* d_out, int out_size) {
    if (!g_init) {
        cudaGetSymbolAddress((void**)&P_x1,  g_x1);
        cudaGetSymbolAddress((void**)&P_A,   g_A);
        cudaGetSymbolAddress((void**)&P_Bm,  g_Bm);
        cudaGetSymbolAddress((void**)&P_x2,  g_x2);
        cudaGetSymbolAddress((void**)&P_sc,  g_sc);
        cudaGetSymbolAddress((void**)&P_Hp,  g_Hp);
        cudaGetSymbolAddress((void**)&P_G,   g_G);
        cudaGetSymbolAddress((void**)&P_hh,  g_hh);
        cudaGetSymbolAddress((void**)&P_qh,  g_qh);
        cudaGetSymbolAddress((void**)&P_kh,  g_kh);
        cudaGetSymbolAddress((void**)&P_vh,  g_vh);
        cudaGetSymbolAddress((void**)&P_ctxh,g_ctxh);
        cudaGetSymbolAddress((void**)&P_x1h, g_x1h);
        cudaGetSymbolAddress((void**)&P_fh,  g_fh);
        cudaGetSymbolAddress((void**)&P_ph,  g_ph);
        cudaGetSymbolAddress((void**)&P_Wqh, g_Wqh);
        cudaGetSymbolAddress((void**)&P_Wkh, g_Wkh);
        cudaGetSymbolAddress((void**)&P_Wvh, g_Wvh);
        cudaGetSymbolAddress((void**)&P_Woh, g_Woh);
        cudaGetSymbolAddress((void**)&P_W1h, g_W1h);
        cudaGetSymbolAddress((void**)&P_W2h, g_W2h);
        cudaGetSymbolAddress((void**)&P_E1h, g_E1h);
        cudaGetSymbolAddress((void**)&P_E2h, g_E2h);
        cudaFuncSetAttribute(gemm_h<4,true,true,false>,  cudaFuncAttributeMaxDynamicSharedMemorySize, SM_T);
        cudaFuncSetAttribute(gemm_h<0,false,false,true>, cudaFuncAttributeMaxDynamicSharedMemorySize, SM_NT);
        cudaFuncSetAttribute(gemm_h<3,false,true,true>,  cudaFuncAttributeMaxDynamicSharedMemorySize, SM_NT);
        cudaFuncSetAttribute(gemm_h<2,false,false,true>, cudaFuncAttributeMaxDynamicSharedMemorySize, SM_NT);
        cudaFuncSetAttribute(gemm_h<3,false,true,false>, cudaFuncAttributeMaxDynamicSharedMemorySize, SM_NT);
        cudaFuncSetAttribute(gemm_h<1,false,false,true>, cudaFuncAttributeMaxDynamicSharedMemorySize, SM_NT);
        cudaFuncSetAttribute(gemm_multi, cudaFuncAttributeMaxDynamicSharedMemorySize, SM_NT);
        g_init = true;
    }
    const float* x      = (const float*)d_in[0];
    const float* Wq     = (const float*)d_in[1];
    const float* bq     = (const float*)d_in[2];
    const float* Wk     = (const float*)d_in[3];
    const float* bk     = (const float*)d_in[4];
    const float* Wv     = (const float*)d_in[5];
    const float* bv     = (const float*)d_in[6];
    const float* Wo     = (const float*)d_in[7];
    const float* bo     = (const float*)d_in[8];
    const float* ln1_g  = (const float*)d_in[9];
    const float* ln1_b  = (const float*)d_in[10];
    const float* rel_W1 = (const float*)d_in[11];
    const float* rel_b1 = (const float*)d_in[12];
    const float* rel_W2 = (const float*)d_in[13];
    const float* rel_b2 = (const float*)d_in[14];
    const float* rel_ln_g = (const float*)d_in[15];
    const float* rel_ln_b = (const float*)d_in[16];
    const float* ln2_g  = (const float*)d_in[17];
    const float* ln2_b  = (const float*)d_in[18];
    const float* enc_W1 = (const float*)d_in[19];
    const float* enc_b1 = (const float*)d_in[20];
    const float* enc_W2 = (const float*)d_in[21];
    const float* enc_b2 = (const float*)d_in[22];
    float* out = (float*)d_out;

    const long long SD = (long long)S_ * D_;
    const long long SS = (long long)S_ * S_;
    const int DD = D_ * D_;

    // 0) fused weight conversions (single launch)
    {
        ConvP p;
        p.src[0]=Wq;    p.dst[0]=P_Wqh;
        p.src[1]=Wk;    p.dst[1]=P_Wkh;
        p.src[2]=Wv;    p.dst[2]=P_Wvh;
        p.src[3]=Wo;    p.dst[3]=P_Woh;
        p.src[4]=rel_W1;p.dst[4]=P_W1h;
        p.src[5]=rel_W2;p.dst[5]=P_W2h;
        p.src[6]=enc_W1;p.dst[6]=P_E1h;
        p.src[7]=enc_W2;p.dst[7]=P_E2h;
        int sz[8] = {DD, DD, DD, DD, 2*DD, DD, D_*DFF_, D_*DFF_};
        p.off[0] = 0;
        for (int k = 0; k < 8; k++) p.off[k+1] = p.off[k] + sz[k];
        int total = p.off[8];
        conv_all<<<(total/4 + 255)/256, 256>>>(p);
    }

    // 1) h = LN1(x) -> fp16
    ln_kernel<<<BS_, 256>>>(x, ln1_g, ln1_b, P_hh);
    // 2) fused QKV
    {
        MultiP p;
        p.W[0]=P_Wqh; p.W[1]=P_Wkh; p.W[2]=P_Wvh;
        p.bias[0]=bq; p.bias[1]=bk; p.bias[2]=bv;
        p.C32[0]=p.C32[1]=p.C32[2]=nullptr;
        p.C16[0]=P_qh; p.C16[1]=P_kh; p.C16[2]=P_vh;
        gemm_multi<<<dim3(18,16), 256, SM_NT>>>(P_hh, p, 6, D_, D_);
    }
    // 3) attention
    gemm_h<4,true,true,false><<<dim3(8,8,B_*H_), 256, SM_T>>>(
        P_qh, P_kh, nullptr, nullptr, P_sc, nullptr,
        S_, S_, 64, D_, D_, S_, SD, 64, SD, 64, (long long)H_*SS, SS);
    softmax_k<<<B_*H_*S_, 256>>>(P_sc, P_ph);
    gemm_h<0,false,false,true><<<dim3(1,8,B_*H_), 256, SM_NT>>>(
        P_ph, P_vh, nullptr, nullptr, nullptr, P_ctxh,
        S_, 64, S_, S_, D_, D_, (long long)H_*SS, SS, SD, 64, SD, 64);
    // 4) x1 = x + ctx@Wo + bo
    gemm_h<3,false,true,true><<<dim3(6,16), 256, SM_NT>>>(
        P_ctxh, P_Woh, bo, x, P_x1, P_x1h,
        BS_, D_, D_, D_, D_, D_, 0,0,0,0,0,0);
    // 5) fused A / Bm
    {
        MultiP p;
        p.W[0]=P_W1h; p.W[1]=P_W1h + DD; p.W[2]=nullptr;
        p.bias[0]=rel_b1; p.bias[1]=nullptr; p.bias[2]=nullptr;
        p.C32[0]=P_A; p.C32[1]=P_Bm; p.C32[2]=nullptr;
        p.C16[0]=p.C16[1]=p.C16[2]=nullptr;
        gemm_multi<<<dim3(12,16), 256, SM_NT>>>(P_x1h, p, 6, D_, D_);
    }
    // 6) relation: materialize G once, then clean fp16 GEMM, then reduce
    gelu_mat<<<dim3(2048, 2), 192>>>(P_A, P_Bm, P_G);
    gemm_h<1,false,false,true><<<dim3(6,1024), 256, SM_NT>>>(
        P_G, P_W2h, rel_b2, nullptr, nullptr, P_Hp,
        MREL, D_, D_, D_, D_, D_, 0,0,0,0,0,0);
    relreduce<<<BS_, 256>>>(P_Hp, rel_ln_g, rel_ln_b, P_x1, P_x2, ln2_g, ln2_b, P_hh);
    // 7) FFN
    gemm_h<2,false,false,true><<<dim3(24,16), 256, SM_NT>>>(
        P_hh, P_E1h, enc_b1, nullptr, nullptr, P_fh,
        BS_, DFF_, D_, D_, DFF_, DFF_, 0,0,0,0,0,0);
    gemm_h<3,false,true,false><<<dim3(6,16), 256, SM_NT>>>(
        P_fh, P_E2h, enc_b2, P_x2, out, nullptr,
        BS_, D_, DFF_, DFF_, D_, D_, 0,0,0,0,0,0);
}